// round 2
// baseline (speedup 1.0000x reference)
#include <cuda_runtime.h>

#define EPS 1e-5f

// ---------------- scratch (static device arrays; allocation-free) ----------
__device__ float g_q[8 * 256 * 768];
__device__ float g_k[8 * 256 * 768];
__device__ float g_v[8 * 256 * 768];
__device__ float g_attn[8 * 256 * 768];
__device__ float g_z[8 * 256 * 768];
__device__ float g_sw[8 * 12 * 256 * 256];   // scores, then softmax weights

// ===========================================================================
// K1: fused QKV projection.  A = nodes [2048 x 768] row-major.
// C = A @ W + b, stored [B,N,H]; q additionally scaled by D^-0.5.
// Tiles BM=128, BN=64, BK=16; 256 threads; 8x4 per-thread microtile.
// grid (36, 16): x -> (weight sel, head/col-tile), y -> M tile.
// ===========================================================================
__global__ __launch_bounds__(256) void qkv_gemm(
    const float* __restrict__ A,
    const float* __restrict__ Wq, const float* __restrict__ bq,
    const float* __restrict__ Wk, const float* __restrict__ bk,
    const float* __restrict__ Wv, const float* __restrict__ bv)
{
    __shared__ float As[16][136];
    __shared__ float Bs[16][68];

    const int bxN = blockIdx.x;        // 0..35
    const int bm  = blockIdx.y;        // 0..15
    const int wsel = bxN / 12;
    const int h    = bxN % 12;
    const float* Bw   = (wsel == 0) ? Wq : (wsel == 1) ? Wk : Wv;
    const float* bias = (wsel == 0) ? bq : (wsel == 1) ? bk : bv;
    float* dst        = (wsel == 0) ? g_q : (wsel == 1) ? g_k : g_v;
    const float scale = (wsel == 0) ? 0.125f : 1.0f;   // D^-0.5 = 1/8
    const int cc0 = h * 64;

    const int tid = threadIdx.x;
    const int tm = tid >> 4;   // 0..15 (8 rows each)
    const int tn = tid & 15;   // 0..15 (4 cols each)

    float acc[8][4];
    #pragma unroll
    for (int i = 0; i < 8; i++)
        #pragma unroll
        for (int j = 0; j < 4; j++) acc[i][j] = 0.f;

    for (int k0 = 0; k0 < 768; k0 += 16) {
        #pragma unroll
        for (int e = 0; e < 2; e++) {
            int fid = tid * 2 + e;           // 0..511
            int row = fid >> 2;              // 0..127
            int kq  = fid & 3;
            float4 v = *(const float4*)(A + (size_t)(bm * 128 + row) * 768 + k0 + kq * 4);
            As[kq * 4 + 0][row] = v.x;
            As[kq * 4 + 1][row] = v.y;
            As[kq * 4 + 2][row] = v.z;
            As[kq * 4 + 3][row] = v.w;
        }
        {
            int kk = tid >> 4, c4 = tid & 15;
            *(float4*)&Bs[kk][c4 * 4] =
                *(const float4*)(Bw + (size_t)(k0 + kk) * 768 + cc0 + c4 * 4);
        }
        __syncthreads();
        #pragma unroll
        for (int kk = 0; kk < 16; kk++) {
            float a[8], b[4];
            *(float4*)&a[0] = *(const float4*)&As[kk][tm * 8];
            *(float4*)&a[4] = *(const float4*)&As[kk][tm * 8 + 4];
            *(float4*)&b[0] = *(const float4*)&Bs[kk][tn * 4];
            #pragma unroll
            for (int i = 0; i < 8; i++)
                #pragma unroll
                for (int j = 0; j < 4; j++)
                    acc[i][j] += a[i] * b[j];
        }
        __syncthreads();
    }

    float4 bs4 = *(const float4*)(bias + cc0 + tn * 4);
    #pragma unroll
    for (int i = 0; i < 8; i++) {
        int row = bm * 128 + tm * 8 + i;
        float4 r;
        r.x = (acc[i][0] + bs4.x) * scale;
        r.y = (acc[i][1] + bs4.y) * scale;
        r.z = (acc[i][2] + bs4.z) * scale;
        r.w = (acc[i][3] + bs4.w) * scale;
        *(float4*)(dst + (size_t)row * 768 + cc0 + tn * 4) = r;
    }
}

// ===========================================================================
// K2: content scores S[b,h,q,k] = q[b,h,q,:].k[b,h,k,:] + bias[b,h,q,k]
// 96 batched 256x256x64 GEMMs. Tile 128x128, 256 threads, 8x8 microtile.
// grid (2, 2, 96).
// ===========================================================================
__global__ __launch_bounds__(256) void qk_gemm(const float* __restrict__ bias)
{
    __shared__ float Qs[16][132];   // [d][qrow]
    __shared__ float Ks[16][132];   // [d][krow]

    const int q0 = blockIdx.x * 128;
    const int k0 = blockIdx.y * 128;
    const int bh = blockIdx.z;              // b*12 + h
    const int b  = bh / 12;
    const int h  = bh % 12;

    const int tid = threadIdx.x;
    const int ty = tid >> 4;   // 0..15 (rows ty*8..)
    const int tx = tid & 15;   // 0..15 (cols tx*8..)

    float acc[8][8];
    #pragma unroll
    for (int i = 0; i < 8; i++)
        #pragma unroll
        for (int j = 0; j < 8; j++) acc[i][j] = 0.f;

    const float* Qbase = g_q + (size_t)(b * 256 + q0) * 768 + h * 64;
    const float* Kbase = g_k + (size_t)(b * 256 + k0) * 768 + h * 64;

    for (int d0 = 0; d0 < 64; d0 += 16) {
        #pragma unroll
        for (int e = 0; e < 2; e++) {
            int fid = tid * 2 + e;       // 0..511
            int r  = fid >> 2;           // 0..127
            int c4 = fid & 3;            // cols c4*4
            float4 v = *(const float4*)(Qbase + (size_t)r * 768 + d0 + c4 * 4);
            Qs[c4 * 4 + 0][r] = v.x;
            Qs[c4 * 4 + 1][r] = v.y;
            Qs[c4 * 4 + 2][r] = v.z;
            Qs[c4 * 4 + 3][r] = v.w;
            float4 w = *(const float4*)(Kbase + (size_t)r * 768 + d0 + c4 * 4);
            Ks[c4 * 4 + 0][r] = w.x;
            Ks[c4 * 4 + 1][r] = w.y;
            Ks[c4 * 4 + 2][r] = w.z;
            Ks[c4 * 4 + 3][r] = w.w;
        }
        __syncthreads();
        #pragma unroll
        for (int kk = 0; kk < 16; kk++) {
            float a[8], c[8];
            *(float4*)&a[0] = *(const float4*)&Qs[kk][ty * 8];
            *(float4*)&a[4] = *(const float4*)&Qs[kk][ty * 8 + 4];
            *(float4*)&c[0] = *(const float4*)&Ks[kk][tx * 8];
            *(float4*)&c[4] = *(const float4*)&Ks[kk][tx * 8 + 4];
            #pragma unroll
            for (int i = 0; i < 8; i++)
                #pragma unroll
                for (int j = 0; j < 8; j++)
                    acc[i][j] += a[i] * c[j];
        }
        __syncthreads();
    }

    #pragma unroll
    for (int i = 0; i < 8; i++) {
        size_t rowoff = ((size_t)bh * 256 + q0 + ty * 8 + i) * 256 + k0 + tx * 8;
        #pragma unroll
        for (int j4 = 0; j4 < 2; j4++) {
            float4 bv = *(const float4*)(bias + rowoff + j4 * 4);
            float4 r;
            r.x = acc[i][j4 * 4 + 0] + bv.x;
            r.y = acc[i][j4 * 4 + 1] + bv.y;
            r.z = acc[i][j4 * 4 + 2] + bv.z;
            r.w = acc[i][j4 * 4 + 3] + bv.w;
            *(float4*)(g_sw + rowoff + j4 * 4) = r;
        }
    }
}

// ===========================================================================
// K3: one CTA per (b, q). LN(paths row) -> pn (smem);
// qw = q@Wsk^T; scores = S + qw.pn + q.bsk; softmax (weights -> g_sw);
// wp = w@pn; struct out = wp@Wsv + bsv -> g_attn.
// 512 threads, 186432 B dynamic smem, grid (256, 8).
// ===========================================================================
__global__ __launch_bounds__(512) void attn_struct_kernel(
    const float* __restrict__ paths,
    const float* __restrict__ Wsk, const float* __restrict__ bsk,
    const float* __restrict__ Wsv, const float* __restrict__ bsv,
    const float* __restrict__ gpath, const float* __restrict__ bpath)
{
    extern __shared__ float sm[];
    float* pn  = sm;              // 256*129 = 33024
    float* qs  = pn + 33024;      // 768
    float* qw  = qs + 768;        // 1536 (reused as wp)
    float* ss  = qw + 1536;       // 3072
    float* qcv = ss + 3072;       // 16
    float* wsT = qcv + 16;        // 8192  (Wsk transposed [d][p])
    // total 46608 floats = 186432 bytes

    const int b  = blockIdx.y;
    const int qi = blockIdx.x;
    const int tid  = threadIdx.x;
    const int warp = tid >> 5;
    const int lane = tid & 31;

    // ---- load q row [768] ----
    if (tid < 192)
        *(float4*)(qs + tid * 4) =
            *(const float4*)(g_q + (size_t)(b * 256 + qi) * 768 + tid * 4);

    // ---- load Wsk transposed into smem ----
    #pragma unroll
    for (int e = 0; e < 4; e++) {
        int fid = e * 512 + tid;          // 0..2047
        int p = fid >> 4, d4 = fid & 15;
        float4 w4 = *(const float4*)(Wsk + p * 64 + d4 * 4);
        wsT[(d4 * 4 + 0) * 128 + p] = w4.x;
        wsT[(d4 * 4 + 1) * 128 + p] = w4.y;
        wsT[(d4 * 4 + 2) * 128 + p] = w4.z;
        wsT[(d4 * 4 + 3) * 128 + p] = w4.w;
    }

    // ---- Phase A: layernorm paths[b,qi,:,:] into pn (stride 129) ----
    {
        float4 gp = *(const float4*)(gpath + lane * 4);
        float4 bp = *(const float4*)(bpath + lane * 4);
        const float* prow = paths + (size_t)(b * 256 + qi) * 32768;
        #pragma unroll
        for (int half = 0; half < 2; half++) {
            float4 xv[8];
            #pragma unroll
            for (int i = 0; i < 8; i++) {
                int r = half * 128 + i * 16 + warp;
                xv[i] = *(const float4*)(prow + r * 128 + lane * 4);
            }
            #pragma unroll
            for (int i = 0; i < 8; i++) {
                int r = half * 128 + i * 16 + warp;
                float s  = xv[i].x + xv[i].y + xv[i].z + xv[i].w;
                float sq = xv[i].x * xv[i].x + xv[i].y * xv[i].y +
                           xv[i].z * xv[i].z + xv[i].w * xv[i].w;
                #pragma unroll
                for (int o = 16; o > 0; o >>= 1) {
                    s  += __shfl_xor_sync(0xffffffffu, s,  o);
                    sq += __shfl_xor_sync(0xffffffffu, sq, o);
                }
                float mu  = s * 0.0078125f;
                float var = sq * 0.0078125f - mu * mu;
                float rs  = rsqrtf(var + EPS);
                float* pr = pn + r * 129 + lane * 4;
                pr[0] = (xv[i].x - mu) * rs * gp.x + bp.x;
                pr[1] = (xv[i].y - mu) * rs * gp.y + bp.y;
                pr[2] = (xv[i].z - mu) * rs * gp.z + bp.z;
                pr[3] = (xv[i].w - mu) * rs * gp.w + bp.w;
            }
        }
    }
    __syncthreads();

    // ---- Phase B: qw[h][p] = sum_d q[h,d]*Wsk[p,d];  qc[h] = q[h].bsk ----
    {
        int p = tid & 127, g = tid >> 7;         // g 0..3, h = g*3+j
        float a0 = 0.f, a1 = 0.f, a2 = 0.f;
        const float* q0 = qs + (g * 3 + 0) * 64;
        const float* q1 = qs + (g * 3 + 1) * 64;
        const float* q2 = qs + (g * 3 + 2) * 64;
        #pragma unroll 8
        for (int d = 0; d < 64; d++) {
            float wv = wsT[d * 128 + p];
            a0 += q0[d] * wv; a1 += q1[d] * wv; a2 += q2[d] * wv;
        }
        qw[(g * 3 + 0) * 128 + p] = a0;
        qw[(g * 3 + 1) * 128 + p] = a1;
        qw[(g * 3 + 2) * 128 + p] = a2;
    }
    if (tid < 12) {
        float acc = 0.f;
        const float* qv = qs + tid * 64;
        #pragma unroll 8
        for (int d = 0; d < 64; d++) acc += qv[d] * bsk[d];
        qcv[tid] = acc;
    }
    __syncthreads();

    // ---- Phase C: scores ss[h][k] = S + sum_p qw[h,p]*pn[k,p] + qc[h] ----
    {
        int k = tid & 255, g = tid >> 8;         // g 0..1, h = g*6+j
        float acc[6] = {0.f, 0.f, 0.f, 0.f, 0.f, 0.f};
        const float* pr = pn + k * 129;
        #pragma unroll 4
        for (int p = 0; p < 128; p++) {
            float pv = pr[p];
            #pragma unroll
            for (int j = 0; j < 6; j++)
                acc[j] += qw[(g * 6 + j) * 128 + p] * pv;
        }
        #pragma unroll
        for (int j = 0; j < 6; j++) {
            int h = g * 6 + j;
            float sv = g_sw[((size_t)(b * 12 + h) * 256 + qi) * 256 + k];
            ss[h * 256 + k] = acc[j] + qcv[h] + sv;
        }
    }
    __syncthreads();

    // ---- Phase D: softmax per head; weights -> ss and g_sw ----
    if (warp < 12) {
        float* row = ss + warp * 256;
        float vals[8], m = -1e30f;
        #pragma unroll
        for (int i = 0; i < 8; i++) {
            vals[i] = row[lane + i * 32];
            m = fmaxf(m, vals[i]);
        }
        #pragma unroll
        for (int o = 16; o > 0; o >>= 1)
            m = fmaxf(m, __shfl_xor_sync(0xffffffffu, m, o));
        float s = 0.f;
        #pragma unroll
        for (int i = 0; i < 8; i++) { vals[i] = __expf(vals[i] - m); s += vals[i]; }
        #pragma unroll
        for (int o = 16; o > 0; o >>= 1)
            s += __shfl_xor_sync(0xffffffffu, s, o);
        float inv = 1.f / s;
        float* gw = g_sw + ((size_t)(b * 12 + warp) * 256 + qi) * 256;
        #pragma unroll
        for (int i = 0; i < 8; i++) {
            float w = vals[i] * inv;
            row[lane + i * 32] = w;
            gw[lane + i * 32]  = w;
        }
    }
    __syncthreads();

    // ---- Phase E: wp[h][p] = sum_k w[h,k]*pn[k,p]  (into qw) ----
    {
        int p = tid & 127, g = tid >> 7;
        float a0 = 0.f, a1 = 0.f, a2 = 0.f;
        const float* w0 = ss + (g * 3 + 0) * 256;
        const float* w1 = ss + (g * 3 + 1) * 256;
        const float* w2 = ss + (g * 3 + 2) * 256;
        #pragma unroll 4
        for (int k = 0; k < 256; k++) {
            float pv = pn[k * 129 + p];
            a0 += w0[k] * pv; a1 += w1[k] * pv; a2 += w2[k] * pv;
        }
        qw[(g * 3 + 0) * 128 + p] = a0;
        qw[(g * 3 + 1) * 128 + p] = a1;
        qw[(g * 3 + 2) * 128 + p] = a2;
    }
    __syncthreads();

    // ---- Phase F: struct out[h,d] = sum_p wp[h,p]*Wsv[p,d] + bsv[d] ----
    float* aout = g_attn + (size_t)(b * 256 + qi) * 768;
    #pragma unroll
    for (int e = 0; e < 2; e++) {
        int o = tid + e * 512;
        if (o < 768) {
            int h = o >> 6, d = o & 63;
            const float* wp = qw + h * 128;
            float acc = 0.f;
            #pragma unroll 8
            for (int p = 0; p < 128; p++)
                acc += wp[p] * Wsv[p * 64 + d];
            aout[o] = acc + bsv[d];
        }
    }
}

// ===========================================================================
// K4: content output C[b,h] = W[b,h](256x256) @ V[b,h](256x64),
// accumulated into g_attn. Tile BM=128, BN=64, BK=32; grid (2, 96).
// ===========================================================================
__global__ __launch_bounds__(256) void wv_gemm()
{
    __shared__ float Ws[32][132];   // [k][qrow]
    __shared__ float Vs[32][68];    // [k][d]

    const int q0 = blockIdx.x * 128;
    const int bh = blockIdx.y;
    const int b  = bh / 12;
    const int h  = bh % 12;

    const int tid = threadIdx.x;
    const int tm = tid >> 4;
    const int tn = tid & 15;

    float acc[8][4];
    #pragma unroll
    for (int i = 0; i < 8; i++)
        #pragma unroll
        for (int j = 0; j < 4; j++) acc[i][j] = 0.f;

    const float* Wbase = g_sw + (size_t)bh * 256 * 256;
    const float* Vbase = g_v + (size_t)(b * 256) * 768 + h * 64;

    for (int k0 = 0; k0 < 256; k0 += 32) {
        #pragma unroll
        for (int e = 0; e < 4; e++) {
            int fid = e * 256 + tid;       // 0..1023
            int r  = fid >> 3;             // 0..127
            int c4 = fid & 7;              // cols c4*4 in [0,32)
            float4 v = *(const float4*)(Wbase + (size_t)(q0 + r) * 256 + k0 + c4 * 4);
            Ws[c4 * 4 + 0][r] = v.x;
            Ws[c4 * 4 + 1][r] = v.y;
            Ws[c4 * 4 + 2][r] = v.z;
            Ws[c4 * 4 + 3][r] = v.w;
        }
        #pragma unroll
        for (int e = 0; e < 2; e++) {
            int fid = e * 256 + tid;       // 0..511
            int r  = fid >> 4;             // 0..31
            int c4 = fid & 15;
            *(float4*)&Vs[r][c4 * 4] =
                *(const float4*)(Vbase + (size_t)(k0 + r) * 768 + c4 * 4);
        }
        __syncthreads();
        #pragma unroll
        for (int kk = 0; kk < 32; kk++) {
            float a[8], c[4];
            *(float4*)&a[0] = *(const float4*)&Ws[kk][tm * 8];
            *(float4*)&a[4] = *(const float4*)&Ws[kk][tm * 8 + 4];
            *(float4*)&c[0] = *(const float4*)&Vs[kk][tn * 4];
            #pragma unroll
            for (int i = 0; i < 8; i++)
                #pragma unroll
                for (int j = 0; j < 4; j++)
                    acc[i][j] += a[i] * c[j];
        }
        __syncthreads();
    }

    #pragma unroll
    for (int i = 0; i < 8; i++) {
        float* dst = g_attn + (size_t)(b * 256 + q0 + tm * 8 + i) * 768 + h * 64 + tn * 4;
        float4 old = *(float4*)dst;
        old.x += acc[i][0];
        old.y += acc[i][1];
        old.z += acc[i][2];
        old.w += acc[i][3];
        *(float4*)dst = old;
    }
}

// ===========================================================================
// K5: z = relu(g_attn @ Wo + bo).  grid (12, 16), same tiling as K1.
// ===========================================================================
__global__ __launch_bounds__(256) void wo_gemm(
    const float* __restrict__ Wo, const float* __restrict__ bo)
{
    __shared__ float As[16][136];
    __shared__ float Bs[16][68];

    const int ct = blockIdx.x;   // 0..11
    const int bm = blockIdx.y;   // 0..15
    const int cc0 = ct * 64;

    const int tid = threadIdx.x;
    const int tm = tid >> 4;
    const int tn = tid & 15;

    float acc[8][4];
    #pragma unroll
    for (int i = 0; i < 8; i++)
        #pragma unroll
        for (int j = 0; j < 4; j++) acc[i][j] = 0.f;

    for (int k0 = 0; k0 < 768; k0 += 16) {
        #pragma unroll
        for (int e = 0; e < 2; e++) {
            int fid = tid * 2 + e;
            int row = fid >> 2;
            int kq  = fid & 3;
            float4 v = *(const float4*)(g_attn + (size_t)(bm * 128 + row) * 768 + k0 + kq * 4);
            As[kq * 4 + 0][row] = v.x;
            As[kq * 4 + 1][row] = v.y;
            As[kq * 4 + 2][row] = v.z;
            As[kq * 4 + 3][row] = v.w;
        }
        {
            int kk = tid >> 4, c4 = tid & 15;
            *(float4*)&Bs[kk][c4 * 4] =
                *(const float4*)(Wo + (size_t)(k0 + kk) * 768 + cc0 + c4 * 4);
        }
        __syncthreads();
        #pragma unroll
        for (int kk = 0; kk < 16; kk++) {
            float a[8], b[4];
            *(float4*)&a[0] = *(const float4*)&As[kk][tm * 8];
            *(float4*)&a[4] = *(const float4*)&As[kk][tm * 8 + 4];
            *(float4*)&b[0] = *(const float4*)&Bs[kk][tn * 4];
            #pragma unroll
            for (int i = 0; i < 8; i++)
                #pragma unroll
                for (int j = 0; j < 4; j++)
                    acc[i][j] += a[i] * b[j];
        }
        __syncthreads();
    }

    float4 bs4 = *(const float4*)(bo + cc0 + tn * 4);
    #pragma unroll
    for (int i = 0; i < 8; i++) {
        int row = bm * 128 + tm * 8 + i;
        float4 r;
        r.x = fmaxf(acc[i][0] + bs4.x, 0.f);
        r.y = fmaxf(acc[i][1] + bs4.y, 0.f);
        r.z = fmaxf(acc[i][2] + bs4.z, 0.f);
        r.w = fmaxf(acc[i][3] + bs4.w, 0.f);
        *(float4*)(g_z + (size_t)row * 768 + cc0 + tn * 4) = r;
    }
}

// ===========================================================================
// K6: out = LN(nodes + z, g_out, b_out). One warp per row, grid 256 x 256thr.
// ===========================================================================
__global__ __launch_bounds__(256) void final_ln(
    const float* __restrict__ nodes,
    const float* __restrict__ gout, const float* __restrict__ bout,
    float* __restrict__ out)
{
    const int row  = blockIdx.x * 8 + (threadIdx.x >> 5);
    const int lane = threadIdx.x & 31;
    const float* x1 = nodes + (size_t)row * 768;
    const float* x2 = g_z   + (size_t)row * 768;

    float v[24];
    float s = 0.f, sq = 0.f;
    #pragma unroll
    for (int i = 0; i < 6; i++) {
        float4 a = *(const float4*)(x1 + i * 128 + lane * 4);
        float4 c = *(const float4*)(x2 + i * 128 + lane * 4);
        float t0 = a.x + c.x, t1 = a.y + c.y, t2 = a.z + c.z, t3 = a.w + c.w;
        v[i * 4 + 0] = t0; v[i * 4 + 1] = t1; v[i * 4 + 2] = t2; v[i * 4 + 3] = t3;
        s += t0 + t1 + t2 + t3;
        sq += t0 * t0 + t1 * t1 + t2 * t2 + t3 * t3;
    }
    #pragma unroll
    for (int o = 16; o > 0; o >>= 1) {
        s  += __shfl_xor_sync(0xffffffffu, s,  o);
        sq += __shfl_xor_sync(0xffffffffu, sq, o);
    }
    const float inv = 1.f / 768.f;
    float mu  = s * inv;
    float var = sq * inv - mu * mu;
    float rs  = rsqrtf(var + EPS);

    float* orow = out + (size_t)row * 768;
    #pragma unroll
    for (int i = 0; i < 6; i++) {
        int idx = i * 128 + lane * 4;
        float4 g4 = *(const float4*)(gout + idx);
        float4 b4 = *(const float4*)(bout + idx);
        float4 r;
        r.x = (v[i * 4 + 0] - mu) * rs * g4.x + b4.x;
        r.y = (v[i * 4 + 1] - mu) * rs * g4.y + b4.y;
        r.z = (v[i * 4 + 2] - mu) * rs * g4.z + b4.z;
        r.w = (v[i * 4 + 3] - mu) * rs * g4.w + b4.w;
        *(float4*)(orow + idx) = r;
    }
}

// ===========================================================================
extern "C" void kernel_launch(void* const* d_in, const int* in_sizes, int n_in,
                              void* d_out, int out_size)
{
    const float* nodes = (const float*)d_in[0];
    const float* bias  = (const float*)d_in[1];
    const float* paths = (const float*)d_in[2];
    const float* Wq  = (const float*)d_in[3];
    const float* bq  = (const float*)d_in[4];
    const float* Wk  = (const float*)d_in[5];
    const float* bk  = (const float*)d_in[6];
    const float* Wv  = (const float*)d_in[7];
    const float* bv  = (const float*)d_in[8];
    const float* Wsk = (const float*)d_in[9];
    const float* bsk = (const float*)d_in[10];
    const float* Wsv = (const float*)d_in[11];
    const float* bsv = (const float*)d_in[12];
    const float* Wo  = (const float*)d_in[13];
    const float* bo  = (const float*)d_in[14];
    const float* gpath = (const float*)d_in[15];
    const float* bpath = (const float*)d_in[16];
    const float* gout  = (const float*)d_in[17];
    const float* bout  = (const float*)d_in[18];
    float* out = (float*)d_out;

    cudaFuncSetAttribute(attn_struct_kernel,
                         cudaFuncAttributeMaxDynamicSharedMemorySize,
                         46608 * 4);

    qkv_gemm<<<dim3(36, 16), 256>>>(nodes, Wq, bq, Wk, bk, Wv, bv);
    qk_gemm<<<dim3(2, 2, 96), 256>>>(bias);
    attn_struct_kernel<<<dim3(256, 8), 512, 46608 * 4>>>(
        paths, Wsk, bsk, Wsv, bsv, gpath, bpath);
    wv_gemm<<<dim3(2, 96), 256>>>();
    wo_gemm<<<dim3(12, 16), 256>>>(Wo, bo);
    final_ln<<<256, 256>>>(nodes, gout, bout, out);
}

// round 4
// speedup vs baseline: 1.2472x; 1.2472x over previous
#include <cuda_runtime.h>
#include <cuda_bf16.h>
#include <cstdint>

#define EPS 1e-5f

// ---------------- scratch (static device arrays; allocation-free) ----------
__device__ float g_q[8 * 256 * 768];
__device__ float g_k[8 * 256 * 768];
__device__ float g_v[8 * 256 * 768];
__device__ float g_attn[8 * 256 * 768];
__device__ float g_z[8 * 256 * 768];
__device__ float g_sw[8 * 12 * 256 * 256];            // scores -> softmax weights
__device__ __nv_bfloat16 g_wt_hi[3072 * 768];         // [Wq|Wk|Wv|Wo]^T bf16 hi
__device__ __nv_bfloat16 g_wt_lo[3072 * 768];         // lo residual

__device__ __forceinline__ uint32_t smem_u32(const void* p) {
    uint32_t a;
    asm("{ .reg .u64 t; cvta.to.shared.u64 t, %1; cvt.u32.u64 %0, t; }"
        : "=r"(a) : "l"(p));
    return a;
}
#define SMEM_SWZ(off) ((off) ^ (((off) >> 3) & 0x70))
__device__ __forceinline__ uint32_t pack2bf(__nv_bfloat16 a, __nv_bfloat16 b) {
    return (uint32_t)__bfloat16_as_ushort(a) | ((uint32_t)__bfloat16_as_ushort(b) << 16);
}

#define LDSM4(r, a) asm volatile( \
    "ldmatrix.sync.aligned.m8n8.x4.shared.b16 {%0,%1,%2,%3}, [%4];" \
    : "=r"((r)[0]), "=r"((r)[1]), "=r"((r)[2]), "=r"((r)[3]) : "r"(a))

#define MMA16816(c, a, b0_, b1_) asm volatile( \
    "mma.sync.aligned.m16n8k16.row.col.f32.bf16.bf16.f32 " \
    "{%0,%1,%2,%3}, {%4,%5,%6,%7}, {%8,%9}, {%0,%1,%2,%3};" \
    : "+f"((c)[0]), "+f"((c)[1]), "+f"((c)[2]), "+f"((c)[3]) \
    : "r"((a)[0]), "r"((a)[1]), "r"((a)[2]), "r"((a)[3]), "r"(b0_), "r"(b1_))

// ===========================================================================
// K0: weight prep — transpose [Wq|Wk|Wv|Wo] into [n][k] bf16 hi/lo.
// grid (48, 12), 256 threads; 64x64 tile transpose.
// ===========================================================================
__global__ __launch_bounds__(256) void prep_weights(
    const float* __restrict__ Wq, const float* __restrict__ Wk,
    const float* __restrict__ Wv, const float* __restrict__ Wo)
{
    __shared__ float s[64][65];
    const int n0 = blockIdx.x * 64;
    const int k0 = blockIdx.y * 64;
    const int tid = threadIdx.x;

    const float* src;
    int c0;
    if (n0 < 768)       { src = Wq; c0 = n0; }
    else if (n0 < 1536) { src = Wk; c0 = n0 - 768; }
    else if (n0 < 2304) { src = Wv; c0 = n0 - 1536; }
    else                { src = Wo; c0 = n0 - 2304; }

    #pragma unroll
    for (int i = 0; i < 4; i++) {
        int fid = i * 256 + tid;
        int kk = fid >> 4, nq = fid & 15;
        float4 v = *(const float4*)(src + (size_t)(k0 + kk) * 768 + c0 + nq * 4);
        s[kk][nq * 4 + 0] = v.x;
        s[kk][nq * 4 + 1] = v.y;
        s[kk][nq * 4 + 2] = v.z;
        s[kk][nq * 4 + 3] = v.w;
    }
    __syncthreads();
    #pragma unroll
    for (int i = 0; i < 4; i++) {
        int fid = i * 256 + tid;
        int nn = fid >> 4, kq = fid & 15;
        float v0 = s[kq * 4 + 0][nn], v1 = s[kq * 4 + 1][nn];
        float v2 = s[kq * 4 + 2][nn], v3 = s[kq * 4 + 3][nn];
        __nv_bfloat16 h0 = __float2bfloat16(v0), h1 = __float2bfloat16(v1);
        __nv_bfloat16 h2 = __float2bfloat16(v2), h3 = __float2bfloat16(v3);
        __nv_bfloat16 l0 = __float2bfloat16(v0 - __bfloat162float(h0));
        __nv_bfloat16 l1 = __float2bfloat16(v1 - __bfloat162float(h1));
        __nv_bfloat16 l2 = __float2bfloat16(v2 - __bfloat162float(h2));
        __nv_bfloat16 l3 = __float2bfloat16(v3 - __bfloat162float(h3));
        size_t o = (size_t)(n0 + nn) * 768 + k0 + kq * 4;
        *(uint2*)(g_wt_hi + o) = make_uint2(pack2bf(h0, h1), pack2bf(h2, h3));
        *(uint2*)(g_wt_lo + o) = make_uint2(pack2bf(l0, l1), pack2bf(l2, l3));
    }
}

// ===========================================================================
// K1/K5: HMMA (mma.sync bf16, 3-pass hi/lo split) GEMM:
// C[2048 x N] = A @ W (+bias epilogue). Tile 128x128, 8 warps of 32x64.
// mode 0 = qkv (bias + q-scale, split dst), mode 1 = wo (relu -> g_z).
// smem 64 KB: A_hi | A_lo | B_hi | B_lo, each 128x64 bf16 SW128-swizzled.
// ===========================================================================
#define HG_SMEM 65536
__global__ __launch_bounds__(256) void hmma_gemm(
    const float* __restrict__ A, int wt_row0,
    const float* __restrict__ b0, const float* __restrict__ b1,
    const float* __restrict__ b2, int mode)
{
    extern __shared__ char smem[];
    const int tid  = threadIdx.x;
    const int wid  = tid >> 5;
    const int lane = tid & 31;
    const int m0 = blockIdx.y * 128;
    const int n0 = blockIdx.x * 128;
    const int wm = wid & 3;    // 4 m-groups of 32 rows
    const int wn = wid >> 2;   // 2 n-groups of 64 cols

    const uint32_t a_hi = smem_u32(smem);
    const uint32_t a_lo = a_hi + 16384;
    const uint32_t b_hi = a_hi + 32768;
    const uint32_t b_lo = a_hi + 49152;

    const __nv_bfloat16* WTh = g_wt_hi + (size_t)wt_row0 * 768;
    const __nv_bfloat16* WTl = g_wt_lo + (size_t)wt_row0 * 768;

    float acc[2][8][4];
    #pragma unroll
    for (int t = 0; t < 2; t++)
        #pragma unroll
        for (int n = 0; n < 8; n++)
            #pragma unroll
            for (int j = 0; j < 4; j++) acc[t][n][j] = 0.f;

    const int arow = wm * 32 + (lane & 15);   // + t*16
    const int brow = wn * 64 + (lane & 15);   // + g*16
    const int cbyt = (lane >> 4) * 16;

    for (int kc = 0; kc < 12; kc++) {
        // ---- stage A chunk: fp32 -> bf16 hi/lo, 128x64, swizzled ----
        #pragma unroll
        for (int i = 0; i < 8; i++) {
            int fid = i * 256 + tid;
            int row = fid >> 4, q = fid & 15;
            float4 v = *(const float4*)(A + (size_t)(m0 + row) * 768 + kc * 64 + q * 4);
            __nv_bfloat16 h0 = __float2bfloat16(v.x), h1 = __float2bfloat16(v.y);
            __nv_bfloat16 h2 = __float2bfloat16(v.z), h3 = __float2bfloat16(v.w);
            __nv_bfloat16 l0 = __float2bfloat16(v.x - __bfloat162float(h0));
            __nv_bfloat16 l1 = __float2bfloat16(v.y - __bfloat162float(h1));
            __nv_bfloat16 l2 = __float2bfloat16(v.z - __bfloat162float(h2));
            __nv_bfloat16 l3 = __float2bfloat16(v.w - __bfloat162float(h3));
            uint32_t off = SMEM_SWZ((uint32_t)(row * 128 + q * 8));
            *(uint2*)(smem + off)         = make_uint2(pack2bf(h0, h1), pack2bf(h2, h3));
            *(uint2*)(smem + 16384 + off) = make_uint2(pack2bf(l0, l1), pack2bf(l2, l3));
        }
        // ---- stage B chunk: pre-converted bf16 hi/lo, 128x64 ----
        #pragma unroll
        for (int i = 0; i < 4; i++) {
            int fid = i * 256 + tid;
            int row = fid >> 3, q = fid & 7;
            uint4 vh = *(const uint4*)(WTh + (size_t)(n0 + row) * 768 + kc * 64 + q * 8);
            uint4 vl = *(const uint4*)(WTl + (size_t)(n0 + row) * 768 + kc * 64 + q * 8);
            uint32_t off = SMEM_SWZ((uint32_t)(row * 128 + q * 16));
            *(uint4*)(smem + 32768 + off) = vh;
            *(uint4*)(smem + 49152 + off) = vl;
        }
        __syncthreads();

        #pragma unroll
        for (int ks = 0; ks < 4; ks++) {
            const int kb = ks * 32 + cbyt;
            uint32_t ah[2][4], al[2][4];
            #pragma unroll
            for (int t = 0; t < 2; t++) {
                uint32_t off = SMEM_SWZ((uint32_t)((arow + t * 16) * 128 + kb));
                LDSM4(ah[t], a_hi + off);
                LDSM4(al[t], a_lo + off);
            }
            uint32_t bh[4][4], bl[4][4];
            #pragma unroll
            for (int g = 0; g < 4; g++) {
                uint32_t off = SMEM_SWZ((uint32_t)((brow + g * 16) * 128 + kb));
                LDSM4(bh[g], b_hi + off);
                LDSM4(bl[g], b_lo + off);
            }
            #pragma unroll
            for (int t = 0; t < 2; t++)
                #pragma unroll
                for (int g = 0; g < 4; g++) {
                    // hi*hi
                    MMA16816(acc[t][2 * g + 0], ah[t], bh[g][0], bh[g][2]);
                    MMA16816(acc[t][2 * g + 1], ah[t], bh[g][1], bh[g][3]);
                    // hi*lo
                    MMA16816(acc[t][2 * g + 0], ah[t], bl[g][0], bl[g][2]);
                    MMA16816(acc[t][2 * g + 1], ah[t], bl[g][1], bl[g][3]);
                    // lo*hi
                    MMA16816(acc[t][2 * g + 0], al[t], bh[g][0], bh[g][2]);
                    MMA16816(acc[t][2 * g + 1], al[t], bh[g][1], bh[g][3]);
                }
        }
        __syncthreads();
    }

    // ---- epilogue ----
    if (mode == 0) {
        const int wsel = n0 / 768;
        float* dstb = (wsel == 0) ? g_q : (wsel == 1) ? g_k : g_v;
        const float* bias = (wsel == 0) ? b0 : (wsel == 1) ? b1 : b2;
        const float sc = (wsel == 0) ? 0.125f : 1.0f;
        const int clb = n0 - wsel * 768 + wn * 64;
        #pragma unroll
        for (int t = 0; t < 2; t++) {
            int r0 = m0 + wm * 32 + t * 16 + (lane >> 2);
            #pragma unroll
            for (int nt = 0; nt < 8; nt++) {
                int cl = clb + nt * 8 + (lane & 3) * 2;
                float2 bv = *(const float2*)(bias + cl);
                float2 o0, o1;
                o0.x = (acc[t][nt][0] + bv.x) * sc;
                o0.y = (acc[t][nt][1] + bv.y) * sc;
                o1.x = (acc[t][nt][2] + bv.x) * sc;
                o1.y = (acc[t][nt][3] + bv.y) * sc;
                *(float2*)(dstb + (size_t)r0 * 768 + cl)       = o0;
                *(float2*)(dstb + (size_t)(r0 + 8) * 768 + cl) = o1;
            }
        }
    } else {
        const int gcb = n0 + wn * 64;
        #pragma unroll
        for (int t = 0; t < 2; t++) {
            int r0 = m0 + wm * 32 + t * 16 + (lane >> 2);
            #pragma unroll
            for (int nt = 0; nt < 8; nt++) {
                int gc = gcb + nt * 8 + (lane & 3) * 2;
                float2 bv = *(const float2*)(b0 + gc);
                float2 o0, o1;
                o0.x = fmaxf(acc[t][nt][0] + bv.x, 0.f);
                o0.y = fmaxf(acc[t][nt][1] + bv.y, 0.f);
                o1.x = fmaxf(acc[t][nt][2] + bv.x, 0.f);
                o1.y = fmaxf(acc[t][nt][3] + bv.y, 0.f);
                *(float2*)(g_z + (size_t)r0 * 768 + gc)       = o0;
                *(float2*)(g_z + (size_t)(r0 + 8) * 768 + gc) = o1;
            }
        }
    }
}

// ===========================================================================
// K2: content scores S = q.k + bias  (96 batched 256x256x64). SIMT.
// ===========================================================================
__global__ __launch_bounds__(256) void qk_gemm(const float* __restrict__ bias)
{
    __shared__ float Qs[16][132];
    __shared__ float Ks[16][132];

    const int q0 = blockIdx.x * 128;
    const int k0 = blockIdx.y * 128;
    const int bh = blockIdx.z;
    const int b  = bh / 12;
    const int h  = bh % 12;

    const int tid = threadIdx.x;
    const int ty = tid >> 4;
    const int tx = tid & 15;

    float acc[8][8];
    #pragma unroll
    for (int i = 0; i < 8; i++)
        #pragma unroll
        for (int j = 0; j < 8; j++) acc[i][j] = 0.f;

    const float* Qbase = g_q + (size_t)(b * 256 + q0) * 768 + h * 64;
    const float* Kbase = g_k + (size_t)(b * 256 + k0) * 768 + h * 64;

    for (int d0 = 0; d0 < 64; d0 += 16) {
        #pragma unroll
        for (int e = 0; e < 2; e++) {
            int fid = tid * 2 + e;
            int r  = fid >> 2;
            int c4 = fid & 3;
            float4 v = *(const float4*)(Qbase + (size_t)r * 768 + d0 + c4 * 4);
            Qs[c4 * 4 + 0][r] = v.x; Qs[c4 * 4 + 1][r] = v.y;
            Qs[c4 * 4 + 2][r] = v.z; Qs[c4 * 4 + 3][r] = v.w;
            float4 w = *(const float4*)(Kbase + (size_t)r * 768 + d0 + c4 * 4);
            Ks[c4 * 4 + 0][r] = w.x; Ks[c4 * 4 + 1][r] = w.y;
            Ks[c4 * 4 + 2][r] = w.z; Ks[c4 * 4 + 3][r] = w.w;
        }
        __syncthreads();
        #pragma unroll
        for (int kk = 0; kk < 16; kk++) {
            float a[8], c[8];
            *(float4*)&a[0] = *(const float4*)&Qs[kk][ty * 8];
            *(float4*)&a[4] = *(const float4*)&Qs[kk][ty * 8 + 4];
            *(float4*)&c[0] = *(const float4*)&Ks[kk][tx * 8];
            *(float4*)&c[4] = *(const float4*)&Ks[kk][tx * 8 + 4];
            #pragma unroll
            for (int i = 0; i < 8; i++)
                #pragma unroll
                for (int j = 0; j < 8; j++)
                    acc[i][j] += a[i] * c[j];
        }
        __syncthreads();
    }

    #pragma unroll
    for (int i = 0; i < 8; i++) {
        size_t rowoff = ((size_t)bh * 256 + q0 + ty * 8 + i) * 256 + k0 + tx * 8;
        #pragma unroll
        for (int j4 = 0; j4 < 2; j4++) {
            float4 bv = *(const float4*)(bias + rowoff + j4 * 4);
            float4 r;
            r.x = acc[i][j4 * 4 + 0] + bv.x;
            r.y = acc[i][j4 * 4 + 1] + bv.y;
            r.z = acc[i][j4 * 4 + 2] + bv.z;
            r.w = acc[i][j4 * 4 + 3] + bv.w;
            *(float4*)(g_sw + rowoff + j4 * 4) = r;
        }
    }
}

// ===========================================================================
// K3: per-(b,q) CTA: LN paths -> pn; struct scores; softmax; struct output.
// 512 threads, 189504 B dyn smem, grid (256, 8).
// ===========================================================================
__global__ __launch_bounds__(512) void attn_struct_kernel(
    const float* __restrict__ paths,
    const float* __restrict__ Wsk, const float* __restrict__ bsk,
    const float* __restrict__ Wsv, const float* __restrict__ bsv,
    const float* __restrict__ gpath, const float* __restrict__ bpath)
{
    extern __shared__ float sm[];
    float* pn  = sm;               // 256*132 = 33792
    float* qs  = pn + 33792;       // 768
    float* qw  = qs + 768;         // 1536 (reused as wp)
    float* ss  = qw + 1536;        // 3072
    float* qcv = ss + 3072;        // 16
    float* wsT = qcv + 16;         // 8192
    // total 47376 floats = 189504 bytes

    const int b  = blockIdx.y;
    const int qi = blockIdx.x;
    const int tid  = threadIdx.x;
    const int warp = tid >> 5;
    const int lane = tid & 31;

    if (tid < 192)
        *(float4*)(qs + tid * 4) =
            *(const float4*)(g_q + (size_t)(b * 256 + qi) * 768 + tid * 4);

    #pragma unroll
    for (int e = 0; e < 4; e++) {
        int fid = e * 512 + tid;
        int p = fid >> 4, d4 = fid & 15;
        float4 w4 = *(const float4*)(Wsk + p * 64 + d4 * 4);
        wsT[(d4 * 4 + 0) * 128 + p] = w4.x;
        wsT[(d4 * 4 + 1) * 128 + p] = w4.y;
        wsT[(d4 * 4 + 2) * 128 + p] = w4.z;
        wsT[(d4 * 4 + 3) * 128 + p] = w4.w;
    }

    // ---- Phase A: layernorm paths rows into pn (stride 132) ----
    {
        float4 gp = *(const float4*)(gpath + lane * 4);
        float4 bp = *(const float4*)(bpath + lane * 4);
        const float* prow = paths + (size_t)(b * 256 + qi) * 32768;
        #pragma unroll
        for (int half = 0; half < 2; half++) {
            float4 xv[8];
            #pragma unroll
            for (int i = 0; i < 8; i++) {
                int r = half * 128 + i * 16 + warp;
                xv[i] = *(const float4*)(prow + r * 128 + lane * 4);
            }
            #pragma unroll
            for (int i = 0; i < 8; i++) {
                int r = half * 128 + i * 16 + warp;
                float s  = xv[i].x + xv[i].y + xv[i].z + xv[i].w;
                float sq = xv[i].x * xv[i].x + xv[i].y * xv[i].y +
                           xv[i].z * xv[i].z + xv[i].w * xv[i].w;
                #pragma unroll
                for (int o = 16; o > 0; o >>= 1) {
                    s  += __shfl_xor_sync(0xffffffffu, s,  o);
                    sq += __shfl_xor_sync(0xffffffffu, sq, o);
                }
                float mu  = s * 0.0078125f;
                float var = sq * 0.0078125f - mu * mu;
                float rs  = rsqrtf(var + EPS);
                float4 y;
                y.x = (xv[i].x - mu) * rs * gp.x + bp.x;
                y.y = (xv[i].y - mu) * rs * gp.y + bp.y;
                y.z = (xv[i].z - mu) * rs * gp.z + bp.z;
                y.w = (xv[i].w - mu) * rs * gp.w + bp.w;
                *(float4*)(pn + r * 132 + lane * 4) = y;
            }
        }
    }
    __syncthreads();

    // ---- Phase B: qw[h][p] = sum_d q[h,d]*Wsk[p,d]; qc[h] = q[h].bsk ----
    {
        int p = tid & 127, g = tid >> 7;
        float a0 = 0.f, a1 = 0.f, a2 = 0.f;
        const float* q0 = qs + (g * 3 + 0) * 64;
        const float* q1 = qs + (g * 3 + 1) * 64;
        const float* q2 = qs + (g * 3 + 2) * 64;
        #pragma unroll 8
        for (int d = 0; d < 64; d++) {
            float wv = wsT[d * 128 + p];
            a0 += q0[d] * wv; a1 += q1[d] * wv; a2 += q2[d] * wv;
        }
        qw[(g * 3 + 0) * 128 + p] = a0;
        qw[(g * 3 + 1) * 128 + p] = a1;
        qw[(g * 3 + 2) * 128 + p] = a2;
    }
    if (tid < 12) {
        float acc = 0.f;
        const float* qv = qs + tid * 64;
        #pragma unroll 8
        for (int d = 0; d < 64; d++) acc += qv[d] * bsk[d];
        qcv[tid] = acc;
    }
    __syncthreads();

    // ---- Phase C: ss[h][k] = S + sum_p qw[h,p]*pn[k,p] + qc[h] ----
    {
        int k = tid & 255, g = tid >> 8;
        float acc[6] = {0.f, 0.f, 0.f, 0.f, 0.f, 0.f};
        const float* pr = pn + k * 132;
        #pragma unroll 8
        for (int p0 = 0; p0 < 128; p0 += 4) {
            float4 pv = *(const float4*)(pr + p0);
            #pragma unroll
            for (int j = 0; j < 6; j++) {
                float4 qv = *(const float4*)(qw + (g * 6 + j) * 128 + p0);
                acc[j] += qv.x * pv.x + qv.y * pv.y + qv.z * pv.z + qv.w * pv.w;
            }
        }
        #pragma unroll
        for (int j = 0; j < 6; j++) {
            int h = g * 6 + j;
            float sv = g_sw[((size_t)(b * 12 + h) * 256 + qi) * 256 + k];
            ss[h * 256 + k] = acc[j] + qcv[h] + sv;
        }
    }
    __syncthreads();

    // ---- Phase D: softmax per head; weights -> ss and g_sw ----
    if (warp < 12) {
        float* row = ss + warp * 256;
        float vals[8], m = -1e30f;
        #pragma unroll
        for (int i = 0; i < 8; i++) {
            vals[i] = row[lane + i * 32];
            m = fmaxf(m, vals[i]);
        }
        #pragma unroll
        for (int o = 16; o > 0; o >>= 1)
            m = fmaxf(m, __shfl_xor_sync(0xffffffffu, m, o));
        float s = 0.f;
        #pragma unroll
        for (int i = 0; i < 8; i++) { vals[i] = __expf(vals[i] - m); s += vals[i]; }
        #pragma unroll
        for (int o = 16; o > 0; o >>= 1)
            s += __shfl_xor_sync(0xffffffffu, s, o);
        float inv = 1.f / s;
        float* gw = g_sw + ((size_t)(b * 12 + warp) * 256 + qi) * 256;
        #pragma unroll
        for (int i = 0; i < 8; i++) {
            float w = vals[i] * inv;
            row[lane + i * 32] = w;
            gw[lane + i * 32]  = w;
        }
    }
    __syncthreads();

    // ---- Phase E: wp[h][p] = sum_k w[h,k]*pn[k,p]  (into qw) ----
    {
        int p = tid & 127, g = tid >> 7;
        float a0 = 0.f, a1 = 0.f, a2 = 0.f;
        const float* w0 = ss + (g * 3 + 0) * 256;
        const float* w1 = ss + (g * 3 + 1) * 256;
        const float* w2 = ss + (g * 3 + 2) * 256;
        #pragma unroll 4
        for (int k0 = 0; k0 < 256; k0 += 4) {
            float4 wv0 = *(const float4*)(w0 + k0);
            float4 wv1 = *(const float4*)(w1 + k0);
            float4 wv2 = *(const float4*)(w2 + k0);
            float pv0 = pn[(k0 + 0) * 132 + p];
            float pv1 = pn[(k0 + 1) * 132 + p];
            float pv2 = pn[(k0 + 2) * 132 + p];
            float pv3 = pn[(k0 + 3) * 132 + p];
            a0 += wv0.x * pv0 + wv0.y * pv1 + wv0.z * pv2 + wv0.w * pv3;
            a1 += wv1.x * pv0 + wv1.y * pv1 + wv1.z * pv2 + wv1.w * pv3;
            a2 += wv2.x * pv0 + wv2.y * pv1 + wv2.z * pv2 + wv2.w * pv3;
        }
        qw[(g * 3 + 0) * 128 + p] = a0;
        qw[(g * 3 + 1) * 128 + p] = a1;
        qw[(g * 3 + 2) * 128 + p] = a2;
    }
    __syncthreads();

    // ---- Phase F: struct out[h,d] = sum_p wp[h,p]*Wsv[p,d] + bsv[d] ----
    float* aout = g_attn + (size_t)(b * 256 + qi) * 768;
    #pragma unroll
    for (int e = 0; e < 2; e++) {
        int o = tid + e * 512;
        if (o < 768) {
            int h = o >> 6, d = o & 63;
            const float* wp = qw + h * 128;
            float acc = 0.f;
            #pragma unroll 8
            for (int p = 0; p < 128; p++)
                acc += wp[p] * Wsv[p * 64 + d];
            aout[o] = acc + bsv[d];
        }
    }
}

// ===========================================================================
// K4: content output W @ V accumulated into g_attn. SIMT.
// ===========================================================================
__global__ __launch_bounds__(256) void wv_gemm()
{
    __shared__ float Ws[32][132];
    __shared__ float Vs[32][68];

    const int q0 = blockIdx.x * 128;
    const int bh = blockIdx.y;
    const int b  = bh / 12;
    const int h  = bh % 12;

    const int tid = threadIdx.x;
    const int tm = tid >> 4;
    const int tn = tid & 15;

    float acc[8][4];
    #pragma unroll
    for (int i = 0; i < 8; i++)
        #pragma unroll
        for (int j = 0; j < 4; j++) acc[i][j] = 0.f;

    const float* Wbase = g_sw + (size_t)bh * 256 * 256;
    const float* Vbase = g_v + (size_t)(b * 256) * 768 + h * 64;

    for (int k0 = 0; k0 < 256; k0 += 32) {
        #pragma unroll
        for (int e = 0; e < 4; e++) {
            int fid = e * 256 + tid;
            int r  = fid >> 3;
            int c4 = fid & 7;
            float4 v = *(const float4*)(Wbase + (size_t)(q0 + r) * 256 + k0 + c4 * 4);
            Ws[c4 * 4 + 0][r] = v.x; Ws[c4 * 4 + 1][r] = v.y;
            Ws[c4 * 4 + 2][r] = v.z; Ws[c4 * 4 + 3][r] = v.w;
        }
        #pragma unroll
        for (int e = 0; e < 2; e++) {
            int fid = e * 256 + tid;
            int r  = fid >> 4;
            int c4 = fid & 15;
            *(float4*)&Vs[r][c4 * 4] =
                *(const float4*)(Vbase + (size_t)(k0 + r) * 768 + c4 * 4);
        }
        __syncthreads();
        #pragma unroll
        for (int kk = 0; kk < 32; kk++) {
            float a[8], c[4];
            *(float4*)&a[0] = *(const float4*)&Ws[kk][tm * 8];
            *(float4*)&a[4] = *(const float4*)&Ws[kk][tm * 8 + 4];
            *(float4*)&c[0] = *(const float4*)&Vs[kk][tn * 4];
            #pragma unroll
            for (int i = 0; i < 8; i++)
                #pragma unroll
                for (int j = 0; j < 4; j++)
                    acc[i][j] += a[i] * c[j];
        }
        __syncthreads();
    }

    #pragma unroll
    for (int i = 0; i < 8; i++) {
        float* dst = g_attn + (size_t)(b * 256 + q0 + tm * 8 + i) * 768 + h * 64 + tn * 4;
        float4 old = *(float4*)dst;
        old.x += acc[i][0];
        old.y += acc[i][1];
        old.z += acc[i][2];
        old.w += acc[i][3];
        *(float4*)dst = old;
    }
}

// ===========================================================================
// K6: out = LN(nodes + g_z). One warp per row.
// ===========================================================================
__global__ __launch_bounds__(256) void final_ln(
    const float* __restrict__ nodes,
    const float* __restrict__ gout, const float* __restrict__ bout,
    float* __restrict__ out)
{
    const int row  = blockIdx.x * 8 + (threadIdx.x >> 5);
    const int lane = threadIdx.x & 31;
    const float* x1 = nodes + (size_t)row * 768;
    const float* x2 = g_z   + (size_t)row * 768;

    float v[24];
    float s = 0.f, sq = 0.f;
    #pragma unroll
    for (int i = 0; i < 6; i++) {
        float4 a = *(const float4*)(x1 + i * 128 + lane * 4);
        float4 c = *(const float4*)(x2 + i * 128 + lane * 4);
        float t0 = a.x + c.x, t1 = a.y + c.y, t2 = a.z + c.z, t3 = a.w + c.w;
        v[i * 4 + 0] = t0; v[i * 4 + 1] = t1; v[i * 4 + 2] = t2; v[i * 4 + 3] = t3;
        s += t0 + t1 + t2 + t3;
        sq += t0 * t0 + t1 * t1 + t2 * t2 + t3 * t3;
    }
    #pragma unroll
    for (int o = 16; o > 0; o >>= 1) {
        s  += __shfl_xor_sync(0xffffffffu, s,  o);
        sq += __shfl_xor_sync(0xffffffffu, sq, o);
    }
    const float inv = 1.f / 768.f;
    float mu  = s * inv;
    float var = sq * inv - mu * mu;
    float rs  = rsqrtf(var + EPS);

    float* orow = out + (size_t)row * 768;
    #pragma unroll
    for (int i = 0; i < 6; i++) {
        int idx = i * 128 + lane * 4;
        float4 g4 = *(const float4*)(gout + idx);
        float4 b4 = *(const float4*)(bout + idx);
        float4 r;
        r.x = (v[i * 4 + 0] - mu) * rs * g4.x + b4.x;
        r.y = (v[i * 4 + 1] - mu) * rs * g4.y + b4.y;
        r.z = (v[i * 4 + 2] - mu) * rs * g4.z + b4.z;
        r.w = (v[i * 4 + 3] - mu) * rs * g4.w + b4.w;
        *(float4*)(orow + idx) = r;
    }
}

// ===========================================================================
extern "C" void kernel_launch(void* const* d_in, const int* in_sizes, int n_in,
                              void* d_out, int out_size)
{
    const float* nodes = (const float*)d_in[0];
    const float* bias  = (const float*)d_in[1];
    const float* paths = (const float*)d_in[2];
    const float* Wq  = (const float*)d_in[3];
    const float* bq  = (const float*)d_in[4];
    const float* Wk  = (const float*)d_in[5];
    const float* bk  = (const float*)d_in[6];
    const float* Wv  = (const float*)d_in[7];
    const float* bv  = (const float*)d_in[8];
    const float* Wsk = (const float*)d_in[9];
    const float* bsk = (const float*)d_in[10];
    const float* Wsv = (const float*)d_in[11];
    const float* bsv = (const float*)d_in[12];
    const float* Wo  = (const float*)d_in[13];
    const float* bo  = (const float*)d_in[14];
    const float* gpath = (const float*)d_in[15];
    const float* bpath = (const float*)d_in[16];
    const float* gout  = (const float*)d_in[17];
    const float* bout  = (const float*)d_in[18];
    float* out = (float*)d_out;

    static bool attr_set = false;
    if (!attr_set) {
        cudaFuncSetAttribute(attn_struct_kernel,
                             cudaFuncAttributeMaxDynamicSharedMemorySize, 189504);
        cudaFuncSetAttribute(hmma_gemm,
                             cudaFuncAttributeMaxDynamicSharedMemorySize, HG_SMEM);
        attr_set = true;
    }

    float* fa_global;
    cudaGetSymbolAddress((void**)&fa_global, g_attn);

    prep_weights<<<dim3(48, 12), 256>>>(Wq, Wk, Wv, Wo);
    hmma_gemm<<<dim3(18, 16), 256, HG_SMEM>>>(nodes, 0, bq, bk, bv, 0);
    qk_gemm<<<dim3(2, 2, 96), 256>>>(bias);
    attn_struct_kernel<<<dim3(256, 8), 512, 189504>>>(
        paths, Wsk, bsk, Wsv, bsv, gpath, bpath);
    wv_gemm<<<dim3(2, 96), 256>>>();
    hmma_gemm<<<dim3(6, 16), 256, HG_SMEM>>>(fa_global, 2304, bo, bo, bo, 1);
    final_ln<<<256, 256>>>(nodes, gout, bout, out);
}

// round 5
// speedup vs baseline: 1.6219x; 1.3005x over previous
#include <cuda_runtime.h>
#include <cuda_bf16.h>
#include <cuda_fp16.h>
#include <cstdint>

#define EPS 1e-5f

// ---------------- scratch (static device arrays; allocation-free) ----------
__device__ float g_q[8 * 256 * 768];
__device__ float g_k[8 * 256 * 768];
__device__ float g_v[8 * 256 * 768];
__device__ float g_attn[8 * 256 * 768];
__device__ float g_z[8 * 256 * 768];
__device__ float g_sw[8 * 12 * 256 * 256];            // scores -> softmax weights
__device__ float g_qw[2048 * 12 * 128];               // q @ Wsk^T per (b,q,h)
__device__ float g_qc[2048 * 12];                     // q . bsk
__device__ __nv_bfloat16 g_wt_hi[3072 * 768];         // [Wq|Wk|Wv|Wo]^T bf16 hi
__device__ __nv_bfloat16 g_wt_lo[3072 * 768];         // lo residual

__device__ __forceinline__ uint32_t smem_u32(const void* p) {
    uint32_t a;
    asm("{ .reg .u64 t; cvta.to.shared.u64 t, %1; cvt.u32.u64 %0, t; }"
        : "=r"(a) : "l"(p));
    return a;
}
#define SMEM_SWZ(off) ((off) ^ (((off) >> 3) & 0x70))
__device__ __forceinline__ uint32_t pack2bf(__nv_bfloat16 a, __nv_bfloat16 b) {
    return (uint32_t)__bfloat16_as_ushort(a) | ((uint32_t)__bfloat16_as_ushort(b) << 16);
}

#define LDSM4(r, a) asm volatile( \
    "ldmatrix.sync.aligned.m8n8.x4.shared.b16 {%0,%1,%2,%3}, [%4];" \
    : "=r"((r)[0]), "=r"((r)[1]), "=r"((r)[2]), "=r"((r)[3]) : "r"(a))

#define MMA16816(c, a, b0_, b1_) asm volatile( \
    "mma.sync.aligned.m16n8k16.row.col.f32.bf16.bf16.f32 " \
    "{%0,%1,%2,%3}, {%4,%5,%6,%7}, {%8,%9}, {%0,%1,%2,%3};" \
    : "+f"((c)[0]), "+f"((c)[1]), "+f"((c)[2]), "+f"((c)[3]) \
    : "r"((a)[0]), "r"((a)[1]), "r"((a)[2]), "r"((a)[3]), "r"(b0_), "r"(b1_))

// ===========================================================================
// K0: weight prep — transpose [Wq|Wk|Wv|Wo] into [n][k] bf16 hi/lo.
// ===========================================================================
__global__ __launch_bounds__(256) void prep_weights(
    const float* __restrict__ Wq, const float* __restrict__ Wk,
    const float* __restrict__ Wv, const float* __restrict__ Wo)
{
    __shared__ float s[64][65];
    const int n0 = blockIdx.x * 64;
    const int k0 = blockIdx.y * 64;
    const int tid = threadIdx.x;

    const float* src;
    int c0;
    if (n0 < 768)       { src = Wq; c0 = n0; }
    else if (n0 < 1536) { src = Wk; c0 = n0 - 768; }
    else if (n0 < 2304) { src = Wv; c0 = n0 - 1536; }
    else                { src = Wo; c0 = n0 - 2304; }

    #pragma unroll
    for (int i = 0; i < 4; i++) {
        int fid = i * 256 + tid;
        int kk = fid >> 4, nq = fid & 15;
        float4 v = *(const float4*)(src + (size_t)(k0 + kk) * 768 + c0 + nq * 4);
        s[kk][nq * 4 + 0] = v.x;
        s[kk][nq * 4 + 1] = v.y;
        s[kk][nq * 4 + 2] = v.z;
        s[kk][nq * 4 + 3] = v.w;
    }
    __syncthreads();
    #pragma unroll
    for (int i = 0; i < 4; i++) {
        int fid = i * 256 + tid;
        int nn = fid >> 4, kq = fid & 15;
        float v0 = s[kq * 4 + 0][nn], v1 = s[kq * 4 + 1][nn];
        float v2 = s[kq * 4 + 2][nn], v3 = s[kq * 4 + 3][nn];
        __nv_bfloat16 h0 = __float2bfloat16(v0), h1 = __float2bfloat16(v1);
        __nv_bfloat16 h2 = __float2bfloat16(v2), h3 = __float2bfloat16(v3);
        __nv_bfloat16 l0 = __float2bfloat16(v0 - __bfloat162float(h0));
        __nv_bfloat16 l1 = __float2bfloat16(v1 - __bfloat162float(h1));
        __nv_bfloat16 l2 = __float2bfloat16(v2 - __bfloat162float(h2));
        __nv_bfloat16 l3 = __float2bfloat16(v3 - __bfloat162float(h3));
        size_t o = (size_t)(n0 + nn) * 768 + k0 + kq * 4;
        *(uint2*)(g_wt_hi + o) = make_uint2(pack2bf(h0, h1), pack2bf(h2, h3));
        *(uint2*)(g_wt_lo + o) = make_uint2(pack2bf(l0, l1), pack2bf(l2, l3));
    }
}

// ===========================================================================
// K1/K5: HMMA (mma.sync bf16, 3-pass hi/lo split) GEMM.
// ===========================================================================
#define HG_SMEM 65536
__global__ __launch_bounds__(256) void hmma_gemm(
    const float* __restrict__ A, int wt_row0,
    const float* __restrict__ b0, const float* __restrict__ b1,
    const float* __restrict__ b2, int mode)
{
    extern __shared__ char smem[];
    const int tid  = threadIdx.x;
    const int wid  = tid >> 5;
    const int lane = tid & 31;
    const int m0 = blockIdx.y * 128;
    const int n0 = blockIdx.x * 128;
    const int wm = wid & 3;
    const int wn = wid >> 2;

    const uint32_t a_hi = smem_u32(smem);
    const uint32_t a_lo = a_hi + 16384;
    const uint32_t b_hi = a_hi + 32768;
    const uint32_t b_lo = a_hi + 49152;

    const __nv_bfloat16* WTh = g_wt_hi + (size_t)wt_row0 * 768;
    const __nv_bfloat16* WTl = g_wt_lo + (size_t)wt_row0 * 768;

    float acc[2][8][4];
    #pragma unroll
    for (int t = 0; t < 2; t++)
        #pragma unroll
        for (int n = 0; n < 8; n++)
            #pragma unroll
            for (int j = 0; j < 4; j++) acc[t][n][j] = 0.f;

    const int arow = wm * 32 + (lane & 15);
    const int brow = wn * 64 + (lane & 15);
    const int cbyt = (lane >> 4) * 16;

    for (int kc = 0; kc < 12; kc++) {
        #pragma unroll
        for (int i = 0; i < 8; i++) {
            int fid = i * 256 + tid;
            int row = fid >> 4, q = fid & 15;
            float4 v = *(const float4*)(A + (size_t)(m0 + row) * 768 + kc * 64 + q * 4);
            __nv_bfloat16 h0 = __float2bfloat16(v.x), h1 = __float2bfloat16(v.y);
            __nv_bfloat16 h2 = __float2bfloat16(v.z), h3 = __float2bfloat16(v.w);
            __nv_bfloat16 l0 = __float2bfloat16(v.x - __bfloat162float(h0));
            __nv_bfloat16 l1 = __float2bfloat16(v.y - __bfloat162float(h1));
            __nv_bfloat16 l2 = __float2bfloat16(v.z - __bfloat162float(h2));
            __nv_bfloat16 l3 = __float2bfloat16(v.w - __bfloat162float(h3));
            uint32_t off = SMEM_SWZ((uint32_t)(row * 128 + q * 8));
            *(uint2*)(smem + off)         = make_uint2(pack2bf(h0, h1), pack2bf(h2, h3));
            *(uint2*)(smem + 16384 + off) = make_uint2(pack2bf(l0, l1), pack2bf(l2, l3));
        }
        #pragma unroll
        for (int i = 0; i < 4; i++) {
            int fid = i * 256 + tid;
            int row = fid >> 3, q = fid & 7;
            uint4 vh = *(const uint4*)(WTh + (size_t)(n0 + row) * 768 + kc * 64 + q * 8);
            uint4 vl = *(const uint4*)(WTl + (size_t)(n0 + row) * 768 + kc * 64 + q * 8);
            uint32_t off = SMEM_SWZ((uint32_t)(row * 128 + q * 16));
            *(uint4*)(smem + 32768 + off) = vh;
            *(uint4*)(smem + 49152 + off) = vl;
        }
        __syncthreads();

        #pragma unroll
        for (int ks = 0; ks < 4; ks++) {
            const int kb = ks * 32 + cbyt;
            uint32_t ah[2][4], al[2][4];
            #pragma unroll
            for (int t = 0; t < 2; t++) {
                uint32_t off = SMEM_SWZ((uint32_t)((arow + t * 16) * 128 + kb));
                LDSM4(ah[t], a_hi + off);
                LDSM4(al[t], a_lo + off);
            }
            uint32_t bh[4][4], bl[4][4];
            #pragma unroll
            for (int g = 0; g < 4; g++) {
                uint32_t off = SMEM_SWZ((uint32_t)((brow + g * 16) * 128 + kb));
                LDSM4(bh[g], b_hi + off);
                LDSM4(bl[g], b_lo + off);
            }
            #pragma unroll
            for (int t = 0; t < 2; t++)
                #pragma unroll
                for (int g = 0; g < 4; g++) {
                    MMA16816(acc[t][2 * g + 0], ah[t], bh[g][0], bh[g][2]);
                    MMA16816(acc[t][2 * g + 1], ah[t], bh[g][1], bh[g][3]);
                    MMA16816(acc[t][2 * g + 0], ah[t], bl[g][0], bl[g][2]);
                    MMA16816(acc[t][2 * g + 1], ah[t], bl[g][1], bl[g][3]);
                    MMA16816(acc[t][2 * g + 0], al[t], bh[g][0], bh[g][2]);
                    MMA16816(acc[t][2 * g + 1], al[t], bh[g][1], bh[g][3]);
                }
        }
        __syncthreads();
    }

    if (mode == 0) {
        const int wsel = n0 / 768;
        float* dstb = (wsel == 0) ? g_q : (wsel == 1) ? g_k : g_v;
        const float* bias = (wsel == 0) ? b0 : (wsel == 1) ? b1 : b2;
        const float sc = (wsel == 0) ? 0.125f : 1.0f;
        const int clb = n0 - wsel * 768 + wn * 64;
        #pragma unroll
        for (int t = 0; t < 2; t++) {
            int r0 = m0 + wm * 32 + t * 16 + (lane >> 2);
            #pragma unroll
            for (int nt = 0; nt < 8; nt++) {
                int cl = clb + nt * 8 + (lane & 3) * 2;
                float2 bv = *(const float2*)(bias + cl);
                float2 o0, o1;
                o0.x = (acc[t][nt][0] + bv.x) * sc;
                o0.y = (acc[t][nt][1] + bv.y) * sc;
                o1.x = (acc[t][nt][2] + bv.x) * sc;
                o1.y = (acc[t][nt][3] + bv.y) * sc;
                *(float2*)(dstb + (size_t)r0 * 768 + cl)       = o0;
                *(float2*)(dstb + (size_t)(r0 + 8) * 768 + cl) = o1;
            }
        }
    } else {
        const int gcb = n0 + wn * 64;
        #pragma unroll
        for (int t = 0; t < 2; t++) {
            int r0 = m0 + wm * 32 + t * 16 + (lane >> 2);
            #pragma unroll
            for (int nt = 0; nt < 8; nt++) {
                int gc = gcb + nt * 8 + (lane & 3) * 2;
                float2 bv = *(const float2*)(b0 + gc);
                float2 o0, o1;
                o0.x = fmaxf(acc[t][nt][0] + bv.x, 0.f);
                o0.y = fmaxf(acc[t][nt][1] + bv.y, 0.f);
                o1.x = fmaxf(acc[t][nt][2] + bv.x, 0.f);
                o1.y = fmaxf(acc[t][nt][3] + bv.y, 0.f);
                *(float2*)(g_z + (size_t)r0 * 768 + gc)       = o0;
                *(float2*)(g_z + (size_t)(r0 + 8) * 768 + gc) = o1;
            }
        }
    }
}

// ===========================================================================
// K2: content scores S = q.k + bias  (96 batched 256x256x64). SIMT.
// ===========================================================================
__global__ __launch_bounds__(256) void qk_gemm(const float* __restrict__ bias)
{
    __shared__ float Qs[16][132];
    __shared__ float Ks[16][132];

    const int q0 = blockIdx.x * 128;
    const int k0 = blockIdx.y * 128;
    const int bh = blockIdx.z;
    const int b  = bh / 12;
    const int h  = bh % 12;

    const int tid = threadIdx.x;
    const int ty = tid >> 4;
    const int tx = tid & 15;

    float acc[8][8];
    #pragma unroll
    for (int i = 0; i < 8; i++)
        #pragma unroll
        for (int j = 0; j < 8; j++) acc[i][j] = 0.f;

    const float* Qbase = g_q + (size_t)(b * 256 + q0) * 768 + h * 64;
    const float* Kbase = g_k + (size_t)(b * 256 + k0) * 768 + h * 64;

    for (int d0 = 0; d0 < 64; d0 += 16) {
        #pragma unroll
        for (int e = 0; e < 2; e++) {
            int fid = tid * 2 + e;
            int r  = fid >> 2;
            int c4 = fid & 3;
            float4 v = *(const float4*)(Qbase + (size_t)r * 768 + d0 + c4 * 4);
            Qs[c4 * 4 + 0][r] = v.x; Qs[c4 * 4 + 1][r] = v.y;
            Qs[c4 * 4 + 2][r] = v.z; Qs[c4 * 4 + 3][r] = v.w;
            float4 w = *(const float4*)(Kbase + (size_t)r * 768 + d0 + c4 * 4);
            Ks[c4 * 4 + 0][r] = w.x; Ks[c4 * 4 + 1][r] = w.y;
            Ks[c4 * 4 + 2][r] = w.z; Ks[c4 * 4 + 3][r] = w.w;
        }
        __syncthreads();
        #pragma unroll
        for (int kk = 0; kk < 16; kk++) {
            float a[8], c[8];
            *(float4*)&a[0] = *(const float4*)&Qs[kk][ty * 8];
            *(float4*)&a[4] = *(const float4*)&Qs[kk][ty * 8 + 4];
            *(float4*)&c[0] = *(const float4*)&Ks[kk][tx * 8];
            *(float4*)&c[4] = *(const float4*)&Ks[kk][tx * 8 + 4];
            #pragma unroll
            for (int i = 0; i < 8; i++)
                #pragma unroll
                for (int j = 0; j < 8; j++)
                    acc[i][j] += a[i] * c[j];
        }
        __syncthreads();
    }

    #pragma unroll
    for (int i = 0; i < 8; i++) {
        size_t rowoff = ((size_t)bh * 256 + q0 + ty * 8 + i) * 256 + k0 + tx * 8;
        #pragma unroll
        for (int j4 = 0; j4 < 2; j4++) {
            float4 bv = *(const float4*)(bias + rowoff + j4 * 4);
            float4 r;
            r.x = acc[i][j4 * 4 + 0] + bv.x;
            r.y = acc[i][j4 * 4 + 1] + bv.y;
            r.z = acc[i][j4 * 4 + 2] + bv.z;
            r.w = acc[i][j4 * 4 + 3] + bv.w;
            *(float4*)(g_sw + rowoff + j4 * 4) = r;
        }
    }
}

// ===========================================================================
// K2b: qw[bq,h,p] = sum_d q[bq,h,d]*Wsk[p,d];  qc[bq,h] = q[bq,h,:].bsk
// grid 256, block 256; each CTA does 8 bq rows.
// ===========================================================================
__global__ __launch_bounds__(256) void qw_gemm(
    const float* __restrict__ Wsk, const float* __restrict__ bsk)
{
    __shared__ float wsT[64 * 128];   // [d][p]
    __shared__ float qr[8 * 768];

    const int bq0 = blockIdx.x * 8;
    const int tid = threadIdx.x;

    #pragma unroll
    for (int e = 0; e < 8; e++) {
        int fid = e * 256 + tid;          // 0..2047
        int p = fid >> 4, d4 = fid & 15;
        float4 v = *(const float4*)(Wsk + p * 64 + d4 * 4);
        wsT[(d4 * 4 + 0) * 128 + p] = v.x;
        wsT[(d4 * 4 + 1) * 128 + p] = v.y;
        wsT[(d4 * 4 + 2) * 128 + p] = v.z;
        wsT[(d4 * 4 + 3) * 128 + p] = v.w;
    }
    #pragma unroll
    for (int e = 0; e < 6; e++) {
        int fid = e * 256 + tid;          // 0..1535 float4s
        int r = fid / 192, c = fid % 192;
        *(float4*)(qr + r * 768 + c * 4) =
            *(const float4*)(g_q + (size_t)(bq0 + r) * 768 + c * 4);
    }
    __syncthreads();

    const int p = tid & 127, g = tid >> 7;   // g in 0..1, heads g*6..g*6+5
    for (int r = 0; r < 8; r++) {
        float acc[6] = {0.f, 0.f, 0.f, 0.f, 0.f, 0.f};
        const float* q6 = qr + r * 768 + g * 6 * 64;
        #pragma unroll 8
        for (int d = 0; d < 64; d++) {
            float wv = wsT[d * 128 + p];
            #pragma unroll
            for (int j = 0; j < 6; j++)
                acc[j] += q6[j * 64 + d] * wv;
        }
        #pragma unroll
        for (int j = 0; j < 6; j++)
            g_qw[((size_t)(bq0 + r) * 12 + g * 6 + j) * 128 + p] = acc[j];
    }
    if (tid < 96) {
        int r = tid / 12, h = tid % 12;
        float a = 0.f;
        #pragma unroll 8
        for (int d = 0; d < 64; d++) a += qr[r * 768 + h * 64 + d] * bsk[d];
        g_qc[(size_t)(bq0 + r) * 12 + h] = a;
    }
}

// ===========================================================================
// K3: per-(b,q) CTA. pn in fp16 (stride 138). smem 89,152 B -> 2 CTAs/SM.
// Phases: A LN -> pn; C struct scores + content + bias; D softmax;
// E wp = w@pn; F struct out.
// ===========================================================================
#define PN_STR 138
#define AT_SMEM 89152
__global__ __launch_bounds__(512) void attn_struct_kernel(
    const float* __restrict__ paths,
    const float* __restrict__ Wsv, const float* __restrict__ bsv,
    const float* __restrict__ gpath, const float* __restrict__ bpath)
{
    extern __shared__ char smraw[];
    __half* pn  = (__half*)smraw;                    // 256*138*2 = 70656
    float*  qw  = (float*)(smraw + 70656);           // 12*128*4  = 6144 (later wp)
    float*  ss  = (float*)(smraw + 76800);           // 12*256*4  = 12288
    float*  qcv = (float*)(smraw + 89088);           // 16*4

    const int b  = blockIdx.y;
    const int qi = blockIdx.x;
    const int bq = b * 256 + qi;
    const int tid  = threadIdx.x;
    const int warp = tid >> 5;
    const int lane = tid & 31;

    // ---- load qw + qc from global ----
    if (tid < 384)
        *(float4*)(qw + tid * 4) =
            *(const float4*)(g_qw + (size_t)bq * 1536 + tid * 4);
    if (tid < 12) qcv[tid] = g_qc[(size_t)bq * 12 + tid];

    // ---- Phase A: layernorm paths rows into pn (fp16, stride 138) ----
    {
        float4 gp = *(const float4*)(gpath + lane * 4);
        float4 bp = *(const float4*)(bpath + lane * 4);
        const float* prow = paths + (size_t)bq * 32768;
        #pragma unroll
        for (int half_ = 0; half_ < 2; half_++) {
            float4 xv[8];
            #pragma unroll
            for (int i = 0; i < 8; i++) {
                int r = half_ * 128 + i * 16 + warp;
                xv[i] = *(const float4*)(prow + r * 128 + lane * 4);
            }
            #pragma unroll
            for (int i = 0; i < 8; i++) {
                int r = half_ * 128 + i * 16 + warp;
                float s  = xv[i].x + xv[i].y + xv[i].z + xv[i].w;
                float sq = xv[i].x * xv[i].x + xv[i].y * xv[i].y +
                           xv[i].z * xv[i].z + xv[i].w * xv[i].w;
                #pragma unroll
                for (int o = 16; o > 0; o >>= 1) {
                    s  += __shfl_xor_sync(0xffffffffu, s,  o);
                    sq += __shfl_xor_sync(0xffffffffu, sq, o);
                }
                float mu  = s * 0.0078125f;
                float var = sq * 0.0078125f - mu * mu;
                float rs  = rsqrtf(var + EPS);
                float y0 = (xv[i].x - mu) * rs * gp.x + bp.x;
                float y1 = (xv[i].y - mu) * rs * gp.y + bp.y;
                float y2 = (xv[i].z - mu) * rs * gp.z + bp.z;
                float y3 = (xv[i].w - mu) * rs * gp.w + bp.w;
                __half* pr = pn + r * PN_STR + lane * 4;
                *(__half2*)(pr)     = __floats2half2_rn(y0, y1);
                *(__half2*)(pr + 2) = __floats2half2_rn(y2, y3);
            }
        }
    }
    __syncthreads();

    // ---- Phase C: ss[h][k] = Σ_p qw[h,p]*pn[k,p] + qc[h] + content ----
    {
        const int k = tid & 255, g = tid >> 8;
        float acc[6] = {0.f, 0.f, 0.f, 0.f, 0.f, 0.f};
        const __half* pr = pn + k * PN_STR;
        #pragma unroll 4
        for (int p0 = 0; p0 < 128; p0 += 8) {
            float2 f0 = __half22float2(*(const __half2*)(pr + p0 + 0));
            float2 f1 = __half22float2(*(const __half2*)(pr + p0 + 2));
            float2 f2 = __half22float2(*(const __half2*)(pr + p0 + 4));
            float2 f3 = __half22float2(*(const __half2*)(pr + p0 + 6));
            #pragma unroll
            for (int j = 0; j < 6; j++) {
                const float* qv = qw + (g * 6 + j) * 128 + p0;
                float4 q0 = *(const float4*)(qv);
                float4 q1 = *(const float4*)(qv + 4);
                acc[j] += q0.x * f0.x + q0.y * f0.y + q0.z * f1.x + q0.w * f1.y
                        + q1.x * f2.x + q1.y * f2.y + q1.z * f3.x + q1.w * f3.y;
            }
        }
        #pragma unroll
        for (int j = 0; j < 6; j++) {
            int h = g * 6 + j;
            float sv = g_sw[((size_t)(b * 12 + h) * 256 + qi) * 256 + k];
            ss[h * 256 + k] = acc[j] + qcv[h] + sv;
        }
    }
    __syncthreads();

    // ---- Phase D: softmax per head; weights -> ss and g_sw ----
    if (warp < 12) {
        float* row = ss + warp * 256;
        float vals[8], m = -1e30f;
        #pragma unroll
        for (int i = 0; i < 8; i++) {
            vals[i] = row[lane + i * 32];
            m = fmaxf(m, vals[i]);
        }
        #pragma unroll
        for (int o = 16; o > 0; o >>= 1)
            m = fmaxf(m, __shfl_xor_sync(0xffffffffu, m, o));
        float s = 0.f;
        #pragma unroll
        for (int i = 0; i < 8; i++) { vals[i] = __expf(vals[i] - m); s += vals[i]; }
        #pragma unroll
        for (int o = 16; o > 0; o >>= 1)
            s += __shfl_xor_sync(0xffffffffu, s, o);
        float inv = 1.f / s;
        float* gw = g_sw + ((size_t)(b * 12 + warp) * 256 + qi) * 256;
        #pragma unroll
        for (int i = 0; i < 8; i++) {
            float w = vals[i] * inv;
            row[lane + i * 32] = w;
            gw[lane + i * 32]  = w;
        }
    }
    __syncthreads();

    // ---- Phase E: wp[h][p] = Σ_k w[h,k]*pn[k,p]  (into qw buffer) ----
    {
        const int p = tid & 127, g = tid >> 7;   // 4 groups x 3 heads
        float a0 = 0.f, a1 = 0.f, a2 = 0.f;
        const float* w0 = ss + (g * 3 + 0) * 256;
        const float* w1 = ss + (g * 3 + 1) * 256;
        const float* w2 = ss + (g * 3 + 2) * 256;
        const __half* pc = pn + p;
        #pragma unroll 4
        for (int k0 = 0; k0 < 256; k0 += 4) {
            float4 wv0 = *(const float4*)(w0 + k0);
            float4 wv1 = *(const float4*)(w1 + k0);
            float4 wv2 = *(const float4*)(w2 + k0);
            float pv0 = __half2float(pc[(k0 + 0) * PN_STR]);
            float pv1 = __half2float(pc[(k0 + 1) * PN_STR]);
            float pv2 = __half2float(pc[(k0 + 2) * PN_STR]);
            float pv3 = __half2float(pc[(k0 + 3) * PN_STR]);
            a0 += wv0.x * pv0 + wv0.y * pv1 + wv0.z * pv2 + wv0.w * pv3;
            a1 += wv1.x * pv0 + wv1.y * pv1 + wv1.z * pv2 + wv1.w * pv3;
            a2 += wv2.x * pv0 + wv2.y * pv1 + wv2.z * pv2 + wv2.w * pv3;
        }
        __syncthreads();   // qw buffer reuse: Phase C readers are done
        qw[(g * 3 + 0) * 128 + p] = a0;
        qw[(g * 3 + 1) * 128 + p] = a1;
        qw[(g * 3 + 2) * 128 + p] = a2;
    }
    __syncthreads();

    // ---- Phase F: struct out[h,d] = Σ_p wp[h,p]*Wsv[p,d] + bsv[d] ----
    float* aout = g_attn + (size_t)bq * 768;
    #pragma unroll
    for (int e = 0; e < 2; e++) {
        int o = tid + e * 512;
        if (o < 768) {
            int h = o >> 6, d = o & 63;
            const float* wp = qw + h * 128;
            float acc = 0.f;
            #pragma unroll 8
            for (int p = 0; p < 128; p++)
                acc += wp[p] * Wsv[p * 64 + d];
            aout[o] = acc + bsv[d];
        }
    }
}

// ===========================================================================
// K4: content output W @ V accumulated into g_attn. SIMT.
// ===========================================================================
__global__ __launch_bounds__(256) void wv_gemm()
{
    __shared__ float Ws[32][132];
    __shared__ float Vs[32][68];

    const int q0 = blockIdx.x * 128;
    const int bh = blockIdx.y;
    const int b  = bh / 12;
    const int h  = bh % 12;

    const int tid = threadIdx.x;
    const int tm = tid >> 4;
    const int tn = tid & 15;

    float acc[8][4];
    #pragma unroll
    for (int i = 0; i < 8; i++)
        #pragma unroll
        for (int j = 0; j < 4; j++) acc[i][j] = 0.f;

    const float* Wbase = g_sw + (size_t)bh * 256 * 256;
    const float* Vbase = g_v + (size_t)(b * 256) * 768 + h * 64;

    for (int k0 = 0; k0 < 256; k0 += 32) {
        #pragma unroll
        for (int e = 0; e < 4; e++) {
            int fid = e * 256 + tid;
            int r  = fid >> 3;
            int c4 = fid & 7;
            float4 v = *(const float4*)(Wbase + (size_t)(q0 + r) * 256 + k0 + c4 * 4);
            Ws[c4 * 4 + 0][r] = v.x; Ws[c4 * 4 + 1][r] = v.y;
            Ws[c4 * 4 + 2][r] = v.z; Ws[c4 * 4 + 3][r] = v.w;
        }
        #pragma unroll
        for (int e = 0; e < 2; e++) {
            int fid = e * 256 + tid;
            int r  = fid >> 4;
            int c4 = fid & 15;
            *(float4*)&Vs[r][c4 * 4] =
                *(const float4*)(Vbase + (size_t)(k0 + r) * 768 + c4 * 4);
        }
        __syncthreads();
        #pragma unroll
        for (int kk = 0; kk < 32; kk++) {
            float a[8], c[4];
            *(float4*)&a[0] = *(const float4*)&Ws[kk][tm * 8];
            *(float4*)&a[4] = *(const float4*)&Ws[kk][tm * 8 + 4];
            *(float4*)&c[0] = *(const float4*)&Vs[kk][tn * 4];
            #pragma unroll
            for (int i = 0; i < 8; i++)
                #pragma unroll
                for (int j = 0; j < 4; j++)
                    acc[i][j] += a[i] * c[j];
        }
        __syncthreads();
    }

    #pragma unroll
    for (int i = 0; i < 8; i++) {
        float* dst = g_attn + (size_t)(b * 256 + q0 + tm * 8 + i) * 768 + h * 64 + tn * 4;
        float4 old = *(float4*)dst;
        old.x += acc[i][0];
        old.y += acc[i][1];
        old.z += acc[i][2];
        old.w += acc[i][3];
        *(float4*)dst = old;
    }
}

// ===========================================================================
// K6: out = LN(nodes + g_z). One warp per row.
// ===========================================================================
__global__ __launch_bounds__(256) void final_ln(
    const float* __restrict__ nodes,
    const float* __restrict__ gout, const float* __restrict__ bout,
    float* __restrict__ out)
{
    const int row  = blockIdx.x * 8 + (threadIdx.x >> 5);
    const int lane = threadIdx.x & 31;
    const float* x1 = nodes + (size_t)row * 768;
    const float* x2 = g_z   + (size_t)row * 768;

    float v[24];
    float s = 0.f, sq = 0.f;
    #pragma unroll
    for (int i = 0; i < 6; i++) {
        float4 a = *(const float4*)(x1 + i * 128 + lane * 4);
        float4 c = *(const float4*)(x2 + i * 128 + lane * 4);
        float t0 = a.x + c.x, t1 = a.y + c.y, t2 = a.z + c.z, t3 = a.w + c.w;
        v[i * 4 + 0] = t0; v[i * 4 + 1] = t1; v[i * 4 + 2] = t2; v[i * 4 + 3] = t3;
        s += t0 + t1 + t2 + t3;
        sq += t0 * t0 + t1 * t1 + t2 * t2 + t3 * t3;
    }
    #pragma unroll
    for (int o = 16; o > 0; o >>= 1) {
        s  += __shfl_xor_sync(0xffffffffu, s,  o);
        sq += __shfl_xor_sync(0xffffffffu, sq, o);
    }
    const float inv = 1.f / 768.f;
    float mu  = s * inv;
    float var = sq * inv - mu * mu;
    float rs  = rsqrtf(var + EPS);

    float* orow = out + (size_t)row * 768;
    #pragma unroll
    for (int i = 0; i < 6; i++) {
        int idx = i * 128 + lane * 4;
        float4 g4 = *(const float4*)(gout + idx);
        float4 b4 = *(const float4*)(bout + idx);
        float4 r;
        r.x = (v[i * 4 + 0] - mu) * rs * g4.x + b4.x;
        r.y = (v[i * 4 + 1] - mu) * rs * g4.y + b4.y;
        r.z = (v[i * 4 + 2] - mu) * rs * g4.z + b4.z;
        r.w = (v[i * 4 + 3] - mu) * rs * g4.w + b4.w;
        *(float4*)(orow + idx) = r;
    }
}

// ===========================================================================
extern "C" void kernel_launch(void* const* d_in, const int* in_sizes, int n_in,
                              void* d_out, int out_size)
{
    const float* nodes = (const float*)d_in[0];
    const float* bias  = (const float*)d_in[1];
    const float* paths = (const float*)d_in[2];
    const float* Wq  = (const float*)d_in[3];
    const float* bq  = (const float*)d_in[4];
    const float* Wk  = (const float*)d_in[5];
    const float* bk  = (const float*)d_in[6];
    const float* Wv  = (const float*)d_in[7];
    const float* bv  = (const float*)d_in[8];
    const float* Wsk = (const float*)d_in[9];
    const float* bsk = (const float*)d_in[10];
    const float* Wsv = (const float*)d_in[11];
    const float* bsv = (const float*)d_in[12];
    const float* Wo  = (const float*)d_in[13];
    const float* bo  = (const float*)d_in[14];
    const float* gpath = (const float*)d_in[15];
    const float* bpath = (const float*)d_in[16];
    const float* gout  = (const float*)d_in[17];
    const float* bout  = (const float*)d_in[18];
    float* out = (float*)d_out;

    static bool attr_set = false;
    if (!attr_set) {
        cudaFuncSetAttribute(attn_struct_kernel,
                             cudaFuncAttributeMaxDynamicSharedMemorySize, AT_SMEM);
        cudaFuncSetAttribute(hmma_gemm,
                             cudaFuncAttributeMaxDynamicSharedMemorySize, HG_SMEM);
        attr_set = true;
    }

    float* fa_global;
    cudaGetSymbolAddress((void**)&fa_global, g_attn);

    prep_weights<<<dim3(48, 12), 256>>>(Wq, Wk, Wv, Wo);
    hmma_gemm<<<dim3(18, 16), 256, HG_SMEM>>>(nodes, 0, bq, bk, bv, 0);
    qk_gemm<<<dim3(2, 2, 96), 256>>>(bias);
    qw_gemm<<<256, 256>>>(Wsk, bsk);
    attn_struct_kernel<<<dim3(256, 8), 512, AT_SMEM>>>(
        paths, Wsv, bsv, gpath, bpath);
    wv_gemm<<<dim3(2, 96), 256>>>();
    hmma_gemm<<<dim3(6, 16), 256, HG_SMEM>>>(fa_global, 2304, bo, bo, bo, 1);
    final_ln<<<256, 256>>>(nodes, gout, bout, out);
}

// round 6
// speedup vs baseline: 2.0783x; 1.2814x over previous
#include <cuda_runtime.h>
#include <cuda_bf16.h>
#include <cuda_fp16.h>
#include <cstdint>

#define EPS 1e-5f

// ---------------- scratch (static device arrays; allocation-free) ----------
__device__ float g_q[8 * 256 * 768];
__device__ float g_k[8 * 256 * 768];
__device__ float g_v[8 * 256 * 768];
__device__ float g_attn[8 * 256 * 768];
__device__ float g_z[8 * 256 * 768];
__device__ float g_sw[8 * 12 * 256 * 256];            // scores -> softmax weights
__device__ float g_qw[2048 * 12 * 128];               // q @ Wsk^T per (b,q,h)
__device__ float g_qc[2048 * 12];                     // q . bsk
__device__ __nv_bfloat16 g_wt_hi[3072 * 768];         // [Wq|Wk|Wv|Wo]^T bf16 hi
__device__ __nv_bfloat16 g_wt_lo[3072 * 768];         // lo residual

__device__ __forceinline__ uint32_t smem_u32(const void* p) {
    uint32_t a;
    asm("{ .reg .u64 t; cvta.to.shared.u64 t, %1; cvt.u32.u64 %0, t; }"
        : "=r"(a) : "l"(p));
    return a;
}
#define SMEM_SWZ(off) ((off) ^ (((off) >> 3) & 0x70))
__device__ __forceinline__ uint32_t pack2bf(__nv_bfloat16 a, __nv_bfloat16 b) {
    return (uint32_t)__bfloat16_as_ushort(a) | ((uint32_t)__bfloat16_as_ushort(b) << 16);
}

#define LDSM4(r, a) asm volatile( \
    "ldmatrix.sync.aligned.m8n8.x4.shared.b16 {%0,%1,%2,%3}, [%4];" \
    : "=r"((r)[0]), "=r"((r)[1]), "=r"((r)[2]), "=r"((r)[3]) : "r"(a))

#define LDSM2T(r, a) asm volatile( \
    "ldmatrix.sync.aligned.m8n8.x2.trans.shared.b16 {%0,%1}, [%2];" \
    : "=r"((r)[0]), "=r"((r)[1]) : "r"(a))

#define MMA16816(c, a, b0_, b1_) asm volatile( \
    "mma.sync.aligned.m16n8k16.row.col.f32.bf16.bf16.f32 " \
    "{%0,%1,%2,%3}, {%4,%5,%6,%7}, {%8,%9}, {%0,%1,%2,%3};" \
    : "+f"((c)[0]), "+f"((c)[1]), "+f"((c)[2]), "+f"((c)[3]) \
    : "r"((a)[0]), "r"((a)[1]), "r"((a)[2]), "r"((a)[3]), "r"(b0_), "r"(b1_))

#define MMA16816H(c, a, b0_, b1_) asm volatile( \
    "mma.sync.aligned.m16n8k16.row.col.f32.f16.f16.f32 " \
    "{%0,%1,%2,%3}, {%4,%5,%6,%7}, {%8,%9}, {%0,%1,%2,%3};" \
    : "+f"((c)[0]), "+f"((c)[1]), "+f"((c)[2]), "+f"((c)[3]) \
    : "r"((a)[0]), "r"((a)[1]), "r"((a)[2]), "r"((a)[3]), "r"(b0_), "r"(b1_))

// ===========================================================================
// K0: weight prep — transpose [Wq|Wk|Wv|Wo] into [n][k] bf16 hi/lo.
// ===========================================================================
__global__ __launch_bounds__(256) void prep_weights(
    const float* __restrict__ Wq, const float* __restrict__ Wk,
    const float* __restrict__ Wv, const float* __restrict__ Wo)
{
    __shared__ float s[64][65];
    const int n0 = blockIdx.x * 64;
    const int k0 = blockIdx.y * 64;
    const int tid = threadIdx.x;

    const float* src;
    int c0;
    if (n0 < 768)       { src = Wq; c0 = n0; }
    else if (n0 < 1536) { src = Wk; c0 = n0 - 768; }
    else if (n0 < 2304) { src = Wv; c0 = n0 - 1536; }
    else                { src = Wo; c0 = n0 - 2304; }

    #pragma unroll
    for (int i = 0; i < 4; i++) {
        int fid = i * 256 + tid;
        int kk = fid >> 4, nq = fid & 15;
        float4 v = *(const float4*)(src + (size_t)(k0 + kk) * 768 + c0 + nq * 4);
        s[kk][nq * 4 + 0] = v.x;
        s[kk][nq * 4 + 1] = v.y;
        s[kk][nq * 4 + 2] = v.z;
        s[kk][nq * 4 + 3] = v.w;
    }
    __syncthreads();
    #pragma unroll
    for (int i = 0; i < 4; i++) {
        int fid = i * 256 + tid;
        int nn = fid >> 4, kq = fid & 15;
        float v0 = s[kq * 4 + 0][nn], v1 = s[kq * 4 + 1][nn];
        float v2 = s[kq * 4 + 2][nn], v3 = s[kq * 4 + 3][nn];
        __nv_bfloat16 h0 = __float2bfloat16(v0), h1 = __float2bfloat16(v1);
        __nv_bfloat16 h2 = __float2bfloat16(v2), h3 = __float2bfloat16(v3);
        __nv_bfloat16 l0 = __float2bfloat16(v0 - __bfloat162float(h0));
        __nv_bfloat16 l1 = __float2bfloat16(v1 - __bfloat162float(h1));
        __nv_bfloat16 l2 = __float2bfloat16(v2 - __bfloat162float(h2));
        __nv_bfloat16 l3 = __float2bfloat16(v3 - __bfloat162float(h3));
        size_t o = (size_t)(n0 + nn) * 768 + k0 + kq * 4;
        *(uint2*)(g_wt_hi + o) = make_uint2(pack2bf(h0, h1), pack2bf(h2, h3));
        *(uint2*)(g_wt_lo + o) = make_uint2(pack2bf(l0, l1), pack2bf(l2, l3));
    }
}

// ===========================================================================
// K1/K5: HMMA (mma.sync bf16, 3-pass hi/lo split) GEMM.
// ===========================================================================
#define HG_SMEM 65536
__global__ __launch_bounds__(256) void hmma_gemm(
    const float* __restrict__ A, int wt_row0,
    const float* __restrict__ b0, const float* __restrict__ b1,
    const float* __restrict__ b2, int mode)
{
    extern __shared__ char smem[];
    const int tid  = threadIdx.x;
    const int wid  = tid >> 5;
    const int lane = tid & 31;
    const int m0 = blockIdx.y * 128;
    const int n0 = blockIdx.x * 128;
    const int wm = wid & 3;
    const int wn = wid >> 2;

    const uint32_t a_hi = smem_u32(smem);
    const uint32_t a_lo = a_hi + 16384;
    const uint32_t b_hi = a_hi + 32768;
    const uint32_t b_lo = a_hi + 49152;

    const __nv_bfloat16* WTh = g_wt_hi + (size_t)wt_row0 * 768;
    const __nv_bfloat16* WTl = g_wt_lo + (size_t)wt_row0 * 768;

    float acc[2][8][4];
    #pragma unroll
    for (int t = 0; t < 2; t++)
        #pragma unroll
        for (int n = 0; n < 8; n++)
            #pragma unroll
            for (int j = 0; j < 4; j++) acc[t][n][j] = 0.f;

    const int arow = wm * 32 + (lane & 15);
    const int brow = wn * 64 + (lane & 15);
    const int cbyt = (lane >> 4) * 16;

    for (int kc = 0; kc < 12; kc++) {
        #pragma unroll
        for (int i = 0; i < 8; i++) {
            int fid = i * 256 + tid;
            int row = fid >> 4, q = fid & 15;
            float4 v = *(const float4*)(A + (size_t)(m0 + row) * 768 + kc * 64 + q * 4);
            __nv_bfloat16 h0 = __float2bfloat16(v.x), h1 = __float2bfloat16(v.y);
            __nv_bfloat16 h2 = __float2bfloat16(v.z), h3 = __float2bfloat16(v.w);
            __nv_bfloat16 l0 = __float2bfloat16(v.x - __bfloat162float(h0));
            __nv_bfloat16 l1 = __float2bfloat16(v.y - __bfloat162float(h1));
            __nv_bfloat16 l2 = __float2bfloat16(v.z - __bfloat162float(h2));
            __nv_bfloat16 l3 = __float2bfloat16(v.w - __bfloat162float(h3));
            uint32_t off = SMEM_SWZ((uint32_t)(row * 128 + q * 8));
            *(uint2*)(smem + off)         = make_uint2(pack2bf(h0, h1), pack2bf(h2, h3));
            *(uint2*)(smem + 16384 + off) = make_uint2(pack2bf(l0, l1), pack2bf(l2, l3));
        }
        #pragma unroll
        for (int i = 0; i < 4; i++) {
            int fid = i * 256 + tid;
            int row = fid >> 3, q = fid & 7;
            uint4 vh = *(const uint4*)(WTh + (size_t)(n0 + row) * 768 + kc * 64 + q * 8);
            uint4 vl = *(const uint4*)(WTl + (size_t)(n0 + row) * 768 + kc * 64 + q * 8);
            uint32_t off = SMEM_SWZ((uint32_t)(row * 128 + q * 16));
            *(uint4*)(smem + 32768 + off) = vh;
            *(uint4*)(smem + 49152 + off) = vl;
        }
        __syncthreads();

        #pragma unroll
        for (int ks = 0; ks < 4; ks++) {
            const int kb = ks * 32 + cbyt;
            uint32_t ah[2][4], al[2][4];
            #pragma unroll
            for (int t = 0; t < 2; t++) {
                uint32_t off = SMEM_SWZ((uint32_t)((arow + t * 16) * 128 + kb));
                LDSM4(ah[t], a_hi + off);
                LDSM4(al[t], a_lo + off);
            }
            uint32_t bh[4][4], bl[4][4];
            #pragma unroll
            for (int g = 0; g < 4; g++) {
                uint32_t off = SMEM_SWZ((uint32_t)((brow + g * 16) * 128 + kb));
                LDSM4(bh[g], b_hi + off);
                LDSM4(bl[g], b_lo + off);
            }
            #pragma unroll
            for (int t = 0; t < 2; t++)
                #pragma unroll
                for (int g = 0; g < 4; g++) {
                    MMA16816(acc[t][2 * g + 0], ah[t], bh[g][0], bh[g][2]);
                    MMA16816(acc[t][2 * g + 1], ah[t], bh[g][1], bh[g][3]);
                    MMA16816(acc[t][2 * g + 0], ah[t], bl[g][0], bl[g][2]);
                    MMA16816(acc[t][2 * g + 1], ah[t], bl[g][1], bl[g][3]);
                    MMA16816(acc[t][2 * g + 0], al[t], bh[g][0], bh[g][2]);
                    MMA16816(acc[t][2 * g + 1], al[t], bh[g][1], bh[g][3]);
                }
        }
        __syncthreads();
    }

    if (mode == 0) {
        const int wsel = n0 / 768;
        float* dstb = (wsel == 0) ? g_q : (wsel == 1) ? g_k : g_v;
        const float* bias = (wsel == 0) ? b0 : (wsel == 1) ? b1 : b2;
        const float sc = (wsel == 0) ? 0.125f : 1.0f;
        const int clb = n0 - wsel * 768 + wn * 64;
        #pragma unroll
        for (int t = 0; t < 2; t++) {
            int r0 = m0 + wm * 32 + t * 16 + (lane >> 2);
            #pragma unroll
            for (int nt = 0; nt < 8; nt++) {
                int cl = clb + nt * 8 + (lane & 3) * 2;
                float2 bv = *(const float2*)(bias + cl);
                float2 o0, o1;
                o0.x = (acc[t][nt][0] + bv.x) * sc;
                o0.y = (acc[t][nt][1] + bv.y) * sc;
                o1.x = (acc[t][nt][2] + bv.x) * sc;
                o1.y = (acc[t][nt][3] + bv.y) * sc;
                *(float2*)(dstb + (size_t)r0 * 768 + cl)       = o0;
                *(float2*)(dstb + (size_t)(r0 + 8) * 768 + cl) = o1;
            }
        }
    } else {
        const int gcb = n0 + wn * 64;
        #pragma unroll
        for (int t = 0; t < 2; t++) {
            int r0 = m0 + wm * 32 + t * 16 + (lane >> 2);
            #pragma unroll
            for (int nt = 0; nt < 8; nt++) {
                int gc = gcb + nt * 8 + (lane & 3) * 2;
                float2 bv = *(const float2*)(b0 + gc);
                float2 o0, o1;
                o0.x = fmaxf(acc[t][nt][0] + bv.x, 0.f);
                o0.y = fmaxf(acc[t][nt][1] + bv.y, 0.f);
                o1.x = fmaxf(acc[t][nt][2] + bv.x, 0.f);
                o1.y = fmaxf(acc[t][nt][3] + bv.y, 0.f);
                *(float2*)(g_z + (size_t)r0 * 768 + gc)       = o0;
                *(float2*)(g_z + (size_t)(r0 + 8) * 768 + gc) = o1;
            }
        }
    }
}

// ===========================================================================
// K2: content scores S = q.k + bias  (96 batched 256x256x64). SIMT.
// ===========================================================================
__global__ __launch_bounds__(256) void qk_gemm(const float* __restrict__ bias)
{
    __shared__ float Qs[16][132];
    __shared__ float Ks[16][132];

    const int q0 = blockIdx.x * 128;
    const int k0 = blockIdx.y * 128;
    const int bh = blockIdx.z;
    const int b  = bh / 12;
    const int h  = bh % 12;

    const int tid = threadIdx.x;
    const int ty = tid >> 4;
    const int tx = tid & 15;

    float acc[8][8];
    #pragma unroll
    for (int i = 0; i < 8; i++)
        #pragma unroll
        for (int j = 0; j < 8; j++) acc[i][j] = 0.f;

    const float* Qbase = g_q + (size_t)(b * 256 + q0) * 768 + h * 64;
    const float* Kbase = g_k + (size_t)(b * 256 + k0) * 768 + h * 64;

    for (int d0 = 0; d0 < 64; d0 += 16) {
        #pragma unroll
        for (int e = 0; e < 2; e++) {
            int fid = tid * 2 + e;
            int r  = fid >> 2;
            int c4 = fid & 3;
            float4 v = *(const float4*)(Qbase + (size_t)r * 768 + d0 + c4 * 4);
            Qs[c4 * 4 + 0][r] = v.x; Qs[c4 * 4 + 1][r] = v.y;
            Qs[c4 * 4 + 2][r] = v.z; Qs[c4 * 4 + 3][r] = v.w;
            float4 w = *(const float4*)(Kbase + (size_t)r * 768 + d0 + c4 * 4);
            Ks[c4 * 4 + 0][r] = w.x; Ks[c4 * 4 + 1][r] = w.y;
            Ks[c4 * 4 + 2][r] = w.z; Ks[c4 * 4 + 3][r] = w.w;
        }
        __syncthreads();
        #pragma unroll
        for (int kk = 0; kk < 16; kk++) {
            float a[8], c[8];
            *(float4*)&a[0] = *(const float4*)&Qs[kk][ty * 8];
            *(float4*)&a[4] = *(const float4*)&Qs[kk][ty * 8 + 4];
            *(float4*)&c[0] = *(const float4*)&Ks[kk][tx * 8];
            *(float4*)&c[4] = *(const float4*)&Ks[kk][tx * 8 + 4];
            #pragma unroll
            for (int i = 0; i < 8; i++)
                #pragma unroll
                for (int j = 0; j < 8; j++)
                    acc[i][j] += a[i] * c[j];
        }
        __syncthreads();
    }

    #pragma unroll
    for (int i = 0; i < 8; i++) {
        size_t rowoff = ((size_t)bh * 256 + q0 + ty * 8 + i) * 256 + k0 + tx * 8;
        #pragma unroll
        for (int j4 = 0; j4 < 2; j4++) {
            float4 bv = *(const float4*)(bias + rowoff + j4 * 4);
            float4 r;
            r.x = acc[i][j4 * 4 + 0] + bv.x;
            r.y = acc[i][j4 * 4 + 1] + bv.y;
            r.z = acc[i][j4 * 4 + 2] + bv.z;
            r.w = acc[i][j4 * 4 + 3] + bv.w;
            *(float4*)(g_sw + rowoff + j4 * 4) = r;
        }
    }
}

// ===========================================================================
// K2b: qw[bq,h,p] = sum_d q[bq,h,d]*Wsk[p,d];  qc[bq,h] = q[bq,h,:].bsk
// ===========================================================================
__global__ __launch_bounds__(256) void qw_gemm(
    const float* __restrict__ Wsk, const float* __restrict__ bsk)
{
    __shared__ float wsT[64 * 128];   // [d][p]
    __shared__ float qr[8 * 768];

    const int bq0 = blockIdx.x * 8;
    const int tid = threadIdx.x;

    #pragma unroll
    for (int e = 0; e < 8; e++) {
        int fid = e * 256 + tid;
        int p = fid >> 4, d4 = fid & 15;
        float4 v = *(const float4*)(Wsk + p * 64 + d4 * 4);
        wsT[(d4 * 4 + 0) * 128 + p] = v.x;
        wsT[(d4 * 4 + 1) * 128 + p] = v.y;
        wsT[(d4 * 4 + 2) * 128 + p] = v.z;
        wsT[(d4 * 4 + 3) * 128 + p] = v.w;
    }
    #pragma unroll
    for (int e = 0; e < 6; e++) {
        int fid = e * 256 + tid;
        int r = fid / 192, c = fid % 192;
        *(float4*)(qr + r * 768 + c * 4) =
            *(const float4*)(g_q + (size_t)(bq0 + r) * 768 + c * 4);
    }
    __syncthreads();

    const int p = tid & 127, g = tid >> 7;
    for (int r = 0; r < 8; r++) {
        float acc[6] = {0.f, 0.f, 0.f, 0.f, 0.f, 0.f};
        const float* q6 = qr + r * 768 + g * 6 * 64;
        #pragma unroll 8
        for (int d = 0; d < 64; d++) {
            float wv = wsT[d * 128 + p];
            #pragma unroll
            for (int j = 0; j < 6; j++)
                acc[j] += q6[j * 64 + d] * wv;
        }
        #pragma unroll
        for (int j = 0; j < 6; j++)
            g_qw[((size_t)(bq0 + r) * 12 + g * 6 + j) * 128 + p] = acc[j];
    }
    if (tid < 96) {
        int r = tid / 12, h = tid % 12;
        float a = 0.f;
        #pragma unroll 8
        for (int d = 0; d < 64; d++) a += qr[r * 768 + h * 64 + d] * bsk[d];
        g_qc[(size_t)(bq0 + r) * 12 + h] = a;
    }
}

// ===========================================================================
// K3: per-(b,q) CTA. pn fp16 stride 136. Phases C and E on HMMA (m16n8k16).
// smem 94,784 B -> 2 CTAs/SM.
// Layout: pn[256][136]h | qwh[16][136]h | wh[16][264]h | ss/wp[12*256]f | qcv
// ===========================================================================
#define PN_STR 136
#define QW_STR 136
#define WH_STR 264
#define OFF_QWH 69632
#define OFF_WH  73984
#define OFF_SS  82432
#define OFF_QCV 94720
#define AT_SMEM 94784
__global__ __launch_bounds__(512, 2) void attn_struct_kernel(
    const float* __restrict__ paths,
    const float* __restrict__ Wsv, const float* __restrict__ bsv,
    const float* __restrict__ gpath, const float* __restrict__ bpath)
{
    extern __shared__ char smraw[];
    __half* pn  = (__half*)smraw;
    __half* qwh = (__half*)(smraw + OFF_QWH);
    __half* wh  = (__half*)(smraw + OFF_WH);
    float*  ss  = (float*)(smraw + OFF_SS);       // scores, later wp
    float*  qcv = (float*)(smraw + OFF_QCV);
    const uint32_t pn_u  = smem_u32(pn);
    const uint32_t qwh_u = smem_u32(qwh);
    const uint32_t wh_u  = smem_u32(wh);

    const int b  = blockIdx.y;
    const int qi = blockIdx.x;
    const int bq = b * 256 + qi;
    const int tid  = threadIdx.x;
    const int warp = tid >> 5;
    const int lane = tid & 31;

    // ---- init: qwh from g_qw (fp32->fp16), zero pads, qcv ----
    if (tid < 384) {
        int h = (tid * 4) >> 7, p = (tid * 4) & 127;
        float4 v = *(const float4*)(g_qw + (size_t)bq * 1536 + tid * 4);
        __half* d = qwh + h * QW_STR + p;
        *(__half2*)(d)     = __floats2half2_rn(v.x, v.y);
        *(__half2*)(d + 2) = __floats2half2_rn(v.z, v.w);
    } else {
        // zero qwh rows 12..15 (544 halves) and wh rows 12..15 (1056 halves)
        int t = tid - 384;   // 0..127
        #pragma unroll
        for (int i = 0; i < 3; i++) {
            int o = t + i * 128;
            if (o < 272) *((__half2*)(qwh + 12 * QW_STR) + o) = __half2half2(__float2half(0.f));
        }
        #pragma unroll
        for (int i = 0; i < 5; i++) {
            int o = t + i * 128;
            if (o < 528) *((__half2*)(wh + 12 * WH_STR) + o) = __half2half2(__float2half(0.f));
        }
    }
    if (tid < 12) qcv[tid] = g_qc[(size_t)bq * 12 + tid];

    // ---- Phase A: layernorm paths rows into pn (fp16, stride 136) ----
    {
        float4 gp = *(const float4*)(gpath + lane * 4);
        float4 bp = *(const float4*)(bpath + lane * 4);
        const float* prow = paths + (size_t)bq * 32768;
        #pragma unroll
        for (int half_ = 0; half_ < 2; half_++) {
            float4 xv[8];
            #pragma unroll
            for (int i = 0; i < 8; i++) {
                int r = half_ * 128 + i * 16 + warp;
                xv[i] = *(const float4*)(prow + r * 128 + lane * 4);
            }
            #pragma unroll
            for (int i = 0; i < 8; i++) {
                int r = half_ * 128 + i * 16 + warp;
                float s  = xv[i].x + xv[i].y + xv[i].z + xv[i].w;
                float sq = xv[i].x * xv[i].x + xv[i].y * xv[i].y +
                           xv[i].z * xv[i].z + xv[i].w * xv[i].w;
                #pragma unroll
                for (int o = 16; o > 0; o >>= 1) {
                    s  += __shfl_xor_sync(0xffffffffu, s,  o);
                    sq += __shfl_xor_sync(0xffffffffu, sq, o);
                }
                float mu  = s * 0.0078125f;
                float var = sq * 0.0078125f - mu * mu;
                float rs  = rsqrtf(var + EPS);
                float y0 = (xv[i].x - mu) * rs * gp.x + bp.x;
                float y1 = (xv[i].y - mu) * rs * gp.y + bp.y;
                float y2 = (xv[i].z - mu) * rs * gp.z + bp.z;
                float y3 = (xv[i].w - mu) * rs * gp.w + bp.w;
                __half* pr = pn + r * PN_STR + lane * 4;
                *(__half2*)(pr)     = __floats2half2_rn(y0, y1);
                *(__half2*)(pr + 2) = __floats2half2_rn(y2, y3);
            }
        }
    }
    __syncthreads();

    // ---- Phase C (HMMA): ss[h][key] = qw[h,:]·pn[key,:] + qc[h] + content ----
    {
        const int n0 = warp * 16;   // 16 keys per warp
        const uint32_t aaddr = qwh_u + ((lane & 15) * QW_STR + (lane >> 4) * 8) * 2;
        const uint32_t baddr = pn_u + ((n0 + (lane & 15)) * PN_STR + (lane >> 4) * 8) * 2;
        float c0[4] = {0.f, 0.f, 0.f, 0.f};
        float c1[4] = {0.f, 0.f, 0.f, 0.f};
        #pragma unroll
        for (int kc = 0; kc < 8; kc++) {
            uint32_t a[4], bm[4];
            LDSM4(a, aaddr + kc * 32);
            LDSM4(bm, baddr + kc * 32);
            MMA16816H(c0, a, bm[0], bm[2]);
            MMA16816H(c1, a, bm[1], bm[3]);
        }
        const int h0 = lane >> 2;
        const int kk = (lane & 3) * 2;
        const float* swb = g_sw + ((size_t)(b * 12 + h0) * 256 + qi) * 256;
        {
            float2 s0 = *(const float2*)(swb + n0 + kk);
            float2 s1 = *(const float2*)(swb + n0 + 8 + kk);
            float qc0 = qcv[h0];
            ss[h0 * 256 + n0 + kk]     = c0[0] + qc0 + s0.x;
            ss[h0 * 256 + n0 + kk + 1] = c0[1] + qc0 + s0.y;
            ss[h0 * 256 + n0 + 8 + kk]     = c1[0] + qc0 + s1.x;
            ss[h0 * 256 + n0 + 8 + kk + 1] = c1[1] + qc0 + s1.y;
        }
        if (h0 < 4) {
            const int h1 = h0 + 8;
            const float* swb1 = g_sw + ((size_t)(b * 12 + h1) * 256 + qi) * 256;
            float2 s0 = *(const float2*)(swb1 + n0 + kk);
            float2 s1 = *(const float2*)(swb1 + n0 + 8 + kk);
            float qc1 = qcv[h1];
            ss[h1 * 256 + n0 + kk]     = c0[2] + qc1 + s0.x;
            ss[h1 * 256 + n0 + kk + 1] = c0[3] + qc1 + s0.y;
            ss[h1 * 256 + n0 + 8 + kk]     = c1[2] + qc1 + s1.x;
            ss[h1 * 256 + n0 + 8 + kk + 1] = c1[3] + qc1 + s1.y;
        }
    }
    __syncthreads();

    // ---- Phase D: softmax; fp32 weights -> g_sw, fp16 -> wh ----
    if (warp < 12) {
        float* row = ss + warp * 256;
        float vals[8], m = -1e30f;
        #pragma unroll
        for (int i = 0; i < 8; i++) {
            vals[i] = row[lane + i * 32];
            m = fmaxf(m, vals[i]);
        }
        #pragma unroll
        for (int o = 16; o > 0; o >>= 1)
            m = fmaxf(m, __shfl_xor_sync(0xffffffffu, m, o));
        float s = 0.f;
        #pragma unroll
        for (int i = 0; i < 8; i++) { vals[i] = __expf(vals[i] - m); s += vals[i]; }
        #pragma unroll
        for (int o = 16; o > 0; o >>= 1)
            s += __shfl_xor_sync(0xffffffffu, s, o);
        float inv = 1.f / s;
        float* gw = g_sw + ((size_t)(b * 12 + warp) * 256 + qi) * 256;
        __half* whr = wh + warp * WH_STR;
        #pragma unroll
        for (int i = 0; i < 8; i++) {
            float w = vals[i] * inv;
            gw[lane + i * 32]  = w;
            whr[lane + i * 32] = __float2half_rn(w);
        }
    }
    __syncthreads();

    // ---- Phase E (HMMA): wp[h][p] = Σ_k w[h,k]·pn[k,p]  (wp aliases ss) ----
    {
        const int p0 = warp * 8;
        const uint32_t aaddr = wh_u + ((lane & 15) * WH_STR + (lane >> 4) * 8) * 2;
        const uint32_t baddr = pn_u + ((lane & 15) * PN_STR + p0) * 2;
        float c[4] = {0.f, 0.f, 0.f, 0.f};
        #pragma unroll
        for (int kc = 0; kc < 16; kc++) {
            uint32_t a[4], bm[2];
            LDSM4(a, aaddr + kc * 32);
            LDSM2T(bm, baddr + kc * 16 * PN_STR * 2);
            MMA16816H(c, a, bm[0], bm[1]);
        }
        __syncthreads();   // all ss readers done; reuse as wp
        float* wp = ss;
        const int h0 = lane >> 2;
        const int pp = p0 + (lane & 3) * 2;
        wp[h0 * 128 + pp]     = c[0];
        wp[h0 * 128 + pp + 1] = c[1];
        if (h0 < 4) {
            wp[(h0 + 8) * 128 + pp]     = c[2];
            wp[(h0 + 8) * 128 + pp + 1] = c[3];
        }
    }
    __syncthreads();

    // ---- Phase F: struct out[h,d] = Σ_p wp[h,p]*Wsv[p,d] + bsv[d] ----
    const float* wp = ss;
    float* aout = g_attn + (size_t)bq * 768;
    #pragma unroll
    for (int e = 0; e < 2; e++) {
        int o = tid + e * 512;
        if (o < 768) {
            int h = o >> 6, d = o & 63;
            const float* wpr = wp + h * 128;
            float acc = 0.f;
            #pragma unroll 8
            for (int p = 0; p < 128; p++)
                acc += wpr[p] * Wsv[p * 64 + d];
            aout[o] = acc + bsv[d];
        }
    }
}

// ===========================================================================
// K4: content output W @ V accumulated into g_attn. SIMT.
// ===========================================================================
__global__ __launch_bounds__(256) void wv_gemm()
{
    __shared__ float Ws[32][132];
    __shared__ float Vs[32][68];

    const int q0 = blockIdx.x * 128;
    const int bh = blockIdx.y;
    const int b  = bh / 12;
    const int h  = bh % 12;

    const int tid = threadIdx.x;
    const int tm = tid >> 4;
    const int tn = tid & 15;

    float acc[8][4];
    #pragma unroll
    for (int i = 0; i < 8; i++)
        #pragma unroll
        for (int j = 0; j < 4; j++) acc[i][j] = 0.f;

    const float* Wbase = g_sw + (size_t)bh * 256 * 256;
    const float* Vbase = g_v + (size_t)(b * 256) * 768 + h * 64;

    for (int k0 = 0; k0 < 256; k0 += 32) {
        #pragma unroll
        for (int e = 0; e < 4; e++) {
            int fid = e * 256 + tid;
            int r  = fid >> 3;
            int c4 = fid & 7;
            float4 v = *(const float4*)(Wbase + (size_t)(q0 + r) * 256 + k0 + c4 * 4);
            Ws[c4 * 4 + 0][r] = v.x; Ws[c4 * 4 + 1][r] = v.y;
            Ws[c4 * 4 + 2][r] = v.z; Ws[c4 * 4 + 3][r] = v.w;
        }
        #pragma unroll
        for (int e = 0; e < 2; e++) {
            int fid = e * 256 + tid;
            int r  = fid >> 4;
            int c4 = fid & 15;
            *(float4*)&Vs[r][c4 * 4] =
                *(const float4*)(Vbase + (size_t)(k0 + r) * 768 + c4 * 4);
        }
        __syncthreads();
        #pragma unroll
        for (int kk = 0; kk < 32; kk++) {
            float a[8], c[4];
            *(float4*)&a[0] = *(const float4*)&Ws[kk][tm * 8];
            *(float4*)&a[4] = *(const float4*)&Ws[kk][tm * 8 + 4];
            *(float4*)&c[0] = *(const float4*)&Vs[kk][tn * 4];
            #pragma unroll
            for (int i = 0; i < 8; i++)
                #pragma unroll
                for (int j = 0; j < 4; j++)
                    acc[i][j] += a[i] * c[j];
        }
        __syncthreads();
    }

    #pragma unroll
    for (int i = 0; i < 8; i++) {
        float* dst = g_attn + (size_t)(b * 256 + q0 + tm * 8 + i) * 768 + h * 64 + tn * 4;
        float4 old = *(float4*)dst;
        old.x += acc[i][0];
        old.y += acc[i][1];
        old.z += acc[i][2];
        old.w += acc[i][3];
        *(float4*)dst = old;
    }
}

// ===========================================================================
// K6: out = LN(nodes + g_z). One warp per row.
// ===========================================================================
__global__ __launch_bounds__(256) void final_ln(
    const float* __restrict__ nodes,
    const float* __restrict__ gout, const float* __restrict__ bout,
    float* __restrict__ out)
{
    const int row  = blockIdx.x * 8 + (threadIdx.x >> 5);
    const int lane = threadIdx.x & 31;
    const float* x1 = nodes + (size_t)row * 768;
    const float* x2 = g_z   + (size_t)row * 768;

    float v[24];
    float s = 0.f, sq = 0.f;
    #pragma unroll
    for (int i = 0; i < 6; i++) {
        float4 a = *(const float4*)(x1 + i * 128 + lane * 4);
        float4 c = *(const float4*)(x2 + i * 128 + lane * 4);
        float t0 = a.x + c.x, t1 = a.y + c.y, t2 = a.z + c.z, t3 = a.w + c.w;
        v[i * 4 + 0] = t0; v[i * 4 + 1] = t1; v[i * 4 + 2] = t2; v[i * 4 + 3] = t3;
        s += t0 + t1 + t2 + t3;
        sq += t0 * t0 + t1 * t1 + t2 * t2 + t3 * t3;
    }
    #pragma unroll
    for (int o = 16; o > 0; o >>= 1) {
        s  += __shfl_xor_sync(0xffffffffu, s,  o);
        sq += __shfl_xor_sync(0xffffffffu, sq, o);
    }
    const float inv = 1.f / 768.f;
    float mu  = s * inv;
    float var = sq * inv - mu * mu;
    float rs  = rsqrtf(var + EPS);

    float* orow = out + (size_t)row * 768;
    #pragma unroll
    for (int i = 0; i < 6; i++) {
        int idx = i * 128 + lane * 4;
        float4 g4 = *(const float4*)(gout + idx);
        float4 b4 = *(const float4*)(bout + idx);
        float4 r;
        r.x = (v[i * 4 + 0] - mu) * rs * g4.x + b4.x;
        r.y = (v[i * 4 + 1] - mu) * rs * g4.y + b4.y;
        r.z = (v[i * 4 + 2] - mu) * rs * g4.z + b4.z;
        r.w = (v[i * 4 + 3] - mu) * rs * g4.w + b4.w;
        *(float4*)(orow + idx) = r;
    }
}

// ===========================================================================
extern "C" void kernel_launch(void* const* d_in, const int* in_sizes, int n_in,
                              void* d_out, int out_size)
{
    const float* nodes = (const float*)d_in[0];
    const float* bias  = (const float*)d_in[1];
    const float* paths = (const float*)d_in[2];
    const float* Wq  = (const float*)d_in[3];
    const float* bq  = (const float*)d_in[4];
    const float* Wk  = (const float*)d_in[5];
    const float* bk  = (const float*)d_in[6];
    const float* Wv  = (const float*)d_in[7];
    const float* bv  = (const float*)d_in[8];
    const float* Wsk = (const float*)d_in[9];
    const float* bsk = (const float*)d_in[10];
    const float* Wsv = (const float*)d_in[11];
    const float* bsv = (const float*)d_in[12];
    const float* Wo  = (const float*)d_in[13];
    const float* bo  = (const float*)d_in[14];
    const float* gpath = (const float*)d_in[15];
    const float* bpath = (const float*)d_in[16];
    const float* gout  = (const float*)d_in[17];
    const float* bout  = (const float*)d_in[18];
    float* out = (float*)d_out;

    static bool attr_set = false;
    if (!attr_set) {
        cudaFuncSetAttribute(attn_struct_kernel,
                             cudaFuncAttributeMaxDynamicSharedMemorySize, AT_SMEM);
        cudaFuncSetAttribute(hmma_gemm,
                             cudaFuncAttributeMaxDynamicSharedMemorySize, HG_SMEM);
        attr_set = true;
    }

    float* fa_global;
    cudaGetSymbolAddress((void**)&fa_global, g_attn);

    prep_weights<<<dim3(48, 12), 256>>>(Wq, Wk, Wv, Wo);
    hmma_gemm<<<dim3(18, 16), 256, HG_SMEM>>>(nodes, 0, bq, bk, bv, 0);
    qk_gemm<<<dim3(2, 2, 96), 256>>>(bias);
    qw_gemm<<<256, 256>>>(Wsk, bsk);
    attn_struct_kernel<<<dim3(256, 8), 512, AT_SMEM>>>(
        paths, Wsv, bsv, gpath, bpath);
    wv_gemm<<<dim3(2, 96), 256>>>();
    hmma_gemm<<<dim3(6, 16), 256, HG_SMEM>>>(fa_global, 2304, bo, bo, bo, 1);
    final_ln<<<256, 256>>>(nodes, gout, bout, out);
}

// round 7
// speedup vs baseline: 2.3166x; 1.1147x over previous
#include <cuda_runtime.h>
#include <cuda_bf16.h>
#include <cuda_fp16.h>
#include <cstdint>

#define EPS 1e-5f

// ---------------- scratch (static device arrays; allocation-free) ----------
__device__ float g_q[8 * 256 * 768];
__device__ float g_k[8 * 256 * 768];
__device__ float g_v[8 * 256 * 768];
__device__ float g_attn[8 * 256 * 768];
__device__ float g_z[8 * 256 * 768];
__device__ float g_sw[8 * 12 * 256 * 256];            // content scores (+bias)
__device__ __half g_swh[8 * 12 * 256 * 256];          // softmax weights fp16
__device__ __half g_qwh[2048 * 12 * 128];             // q @ Wsk^T fp16
__device__ float g_qc[2048 * 12];                     // q . bsk
__device__ __nv_bfloat16 g_wt_hi[3072 * 768];         // [Wq|Wk|Wv|Wo]^T bf16 hi
__device__ __nv_bfloat16 g_wt_lo[3072 * 768];         // lo residual

__device__ __forceinline__ uint32_t smem_u32(const void* p) {
    uint32_t a;
    asm("{ .reg .u64 t; cvta.to.shared.u64 t, %1; cvt.u32.u64 %0, t; }"
        : "=r"(a) : "l"(p));
    return a;
}
#define SMEM_SWZ(off) ((off) ^ (((off) >> 3) & 0x70))
__device__ __forceinline__ uint32_t pack2bf(__nv_bfloat16 a, __nv_bfloat16 b) {
    return (uint32_t)__bfloat16_as_ushort(a) | ((uint32_t)__bfloat16_as_ushort(b) << 16);
}
__device__ __forceinline__ void cvt_hilo(float4 v, uint2& hi, uint2& lo) {
    __nv_bfloat16 h0 = __float2bfloat16(v.x), h1 = __float2bfloat16(v.y);
    __nv_bfloat16 h2 = __float2bfloat16(v.z), h3 = __float2bfloat16(v.w);
    __nv_bfloat16 l0 = __float2bfloat16(v.x - __bfloat162float(h0));
    __nv_bfloat16 l1 = __float2bfloat16(v.y - __bfloat162float(h1));
    __nv_bfloat16 l2 = __float2bfloat16(v.z - __bfloat162float(h2));
    __nv_bfloat16 l3 = __float2bfloat16(v.w - __bfloat162float(h3));
    hi = make_uint2(pack2bf(h0, h1), pack2bf(h2, h3));
    lo = make_uint2(pack2bf(l0, l1), pack2bf(l2, l3));
}
__device__ __forceinline__ uint32_t pack2h(__half a, __half b) {
    __half2 t = __halves2half2(a, b);
    return *(uint32_t*)&t;
}

#define LDSM4(r, a) asm volatile( \
    "ldmatrix.sync.aligned.m8n8.x4.shared.b16 {%0,%1,%2,%3}, [%4];" \
    : "=r"((r)[0]), "=r"((r)[1]), "=r"((r)[2]), "=r"((r)[3]) : "r"(a))

#define LDSM2T(r, a) asm volatile( \
    "ldmatrix.sync.aligned.m8n8.x2.trans.shared.b16 {%0,%1}, [%2];" \
    : "=r"((r)[0]), "=r"((r)[1]) : "r"(a))

#define MMA16816(c, a, b0_, b1_) asm volatile( \
    "mma.sync.aligned.m16n8k16.row.col.f32.bf16.bf16.f32 " \
    "{%0,%1,%2,%3}, {%4,%5,%6,%7}, {%8,%9}, {%0,%1,%2,%3};" \
    : "+f"((c)[0]), "+f"((c)[1]), "+f"((c)[2]), "+f"((c)[3]) \
    : "r"((a)[0]), "r"((a)[1]), "r"((a)[2]), "r"((a)[3]), "r"(b0_), "r"(b1_))

#define MMA16816H(c, a, b0_, b1_) asm volatile( \
    "mma.sync.aligned.m16n8k16.row.col.f32.f16.f16.f32 " \
    "{%0,%1,%2,%3}, {%4,%5,%6,%7}, {%8,%9}, {%0,%1,%2,%3};" \
    : "+f"((c)[0]), "+f"((c)[1]), "+f"((c)[2]), "+f"((c)[3]) \
    : "r"((a)[0]), "r"((a)[1]), "r"((a)[2]), "r"((a)[3]), "r"(b0_), "r"(b1_))

// ===========================================================================
// K0: weight prep — transpose [Wq|Wk|Wv|Wo] into [n][k] bf16 hi/lo.
// ===========================================================================
__global__ __launch_bounds__(256) void prep_weights(
    const float* __restrict__ Wq, const float* __restrict__ Wk,
    const float* __restrict__ Wv, const float* __restrict__ Wo)
{
    __shared__ float s[64][65];
    const int n0 = blockIdx.x * 64;
    const int k0 = blockIdx.y * 64;
    const int tid = threadIdx.x;

    const float* src;
    int c0;
    if (n0 < 768)       { src = Wq; c0 = n0; }
    else if (n0 < 1536) { src = Wk; c0 = n0 - 768; }
    else if (n0 < 2304) { src = Wv; c0 = n0 - 1536; }
    else                { src = Wo; c0 = n0 - 2304; }

    #pragma unroll
    for (int i = 0; i < 4; i++) {
        int fid = i * 256 + tid;
        int kk = fid >> 4, nq = fid & 15;
        float4 v = *(const float4*)(src + (size_t)(k0 + kk) * 768 + c0 + nq * 4);
        s[kk][nq * 4 + 0] = v.x;
        s[kk][nq * 4 + 1] = v.y;
        s[kk][nq * 4 + 2] = v.z;
        s[kk][nq * 4 + 3] = v.w;
    }
    __syncthreads();
    #pragma unroll
    for (int i = 0; i < 4; i++) {
        int fid = i * 256 + tid;
        int nn = fid >> 4, kq = fid & 15;
        float4 v = make_float4(s[kq * 4 + 0][nn], s[kq * 4 + 1][nn],
                               s[kq * 4 + 2][nn], s[kq * 4 + 3][nn]);
        uint2 hi, lo;
        cvt_hilo(v, hi, lo);
        size_t o = (size_t)(n0 + nn) * 768 + k0 + kq * 4;
        *(uint2*)(g_wt_hi + o) = hi;
        *(uint2*)(g_wt_lo + o) = lo;
    }
}

// ===========================================================================
// K1/K7: HMMA (mma.sync bf16, 3-pass hi/lo split) GEMM for A@W.
// ===========================================================================
#define HG_SMEM 65536
__global__ __launch_bounds__(256) void hmma_gemm(
    const float* __restrict__ A, int wt_row0,
    const float* __restrict__ b0, const float* __restrict__ b1,
    const float* __restrict__ b2, int mode)
{
    extern __shared__ char smem[];
    const int tid  = threadIdx.x;
    const int wid  = tid >> 5;
    const int lane = tid & 31;
    const int m0 = blockIdx.y * 128;
    const int n0 = blockIdx.x * 128;
    const int wm = wid & 3;
    const int wn = wid >> 2;

    const uint32_t a_hi = smem_u32(smem);
    const uint32_t a_lo = a_hi + 16384;
    const uint32_t b_hi = a_hi + 32768;
    const uint32_t b_lo = a_hi + 49152;

    const __nv_bfloat16* WTh = g_wt_hi + (size_t)wt_row0 * 768;
    const __nv_bfloat16* WTl = g_wt_lo + (size_t)wt_row0 * 768;

    float acc[2][8][4];
    #pragma unroll
    for (int t = 0; t < 2; t++)
        #pragma unroll
        for (int n = 0; n < 8; n++)
            #pragma unroll
            for (int j = 0; j < 4; j++) acc[t][n][j] = 0.f;

    const int arow = wm * 32 + (lane & 15);
    const int brow = wn * 64 + (lane & 15);
    const int cbyt = (lane >> 4) * 16;

    for (int kc = 0; kc < 12; kc++) {
        #pragma unroll
        for (int i = 0; i < 8; i++) {
            int fid = i * 256 + tid;
            int row = fid >> 4, q = fid & 15;
            float4 v = *(const float4*)(A + (size_t)(m0 + row) * 768 + kc * 64 + q * 4);
            uint2 hi, lo;
            cvt_hilo(v, hi, lo);
            uint32_t off = SMEM_SWZ((uint32_t)(row * 128 + q * 8));
            *(uint2*)(smem + off)         = hi;
            *(uint2*)(smem + 16384 + off) = lo;
        }
        #pragma unroll
        for (int i = 0; i < 4; i++) {
            int fid = i * 256 + tid;
            int row = fid >> 3, q = fid & 7;
            uint4 vh = *(const uint4*)(WTh + (size_t)(n0 + row) * 768 + kc * 64 + q * 8);
            uint4 vl = *(const uint4*)(WTl + (size_t)(n0 + row) * 768 + kc * 64 + q * 8);
            uint32_t off = SMEM_SWZ((uint32_t)(row * 128 + q * 16));
            *(uint4*)(smem + 32768 + off) = vh;
            *(uint4*)(smem + 49152 + off) = vl;
        }
        __syncthreads();

        #pragma unroll
        for (int ks = 0; ks < 4; ks++) {
            const int kb = ks * 32 + cbyt;
            uint32_t ah[2][4], al[2][4];
            #pragma unroll
            for (int t = 0; t < 2; t++) {
                uint32_t off = SMEM_SWZ((uint32_t)((arow + t * 16) * 128 + kb));
                LDSM4(ah[t], a_hi + off);
                LDSM4(al[t], a_lo + off);
            }
            uint32_t bh[4][4], bl[4][4];
            #pragma unroll
            for (int g = 0; g < 4; g++) {
                uint32_t off = SMEM_SWZ((uint32_t)((brow + g * 16) * 128 + kb));
                LDSM4(bh[g], b_hi + off);
                LDSM4(bl[g], b_lo + off);
            }
            #pragma unroll
            for (int t = 0; t < 2; t++)
                #pragma unroll
                for (int g = 0; g < 4; g++) {
                    MMA16816(acc[t][2 * g + 0], ah[t], bh[g][0], bh[g][2]);
                    MMA16816(acc[t][2 * g + 1], ah[t], bh[g][1], bh[g][3]);
                    MMA16816(acc[t][2 * g + 0], ah[t], bl[g][0], bl[g][2]);
                    MMA16816(acc[t][2 * g + 1], ah[t], bl[g][1], bl[g][3]);
                    MMA16816(acc[t][2 * g + 0], al[t], bh[g][0], bh[g][2]);
                    MMA16816(acc[t][2 * g + 1], al[t], bh[g][1], bh[g][3]);
                }
        }
        __syncthreads();
    }

    if (mode == 0) {
        const int wsel = n0 / 768;
        float* dstb = (wsel == 0) ? g_q : (wsel == 1) ? g_k : g_v;
        const float* bias = (wsel == 0) ? b0 : (wsel == 1) ? b1 : b2;
        const float sc = (wsel == 0) ? 0.125f : 1.0f;
        const int clb = n0 - wsel * 768 + wn * 64;
        #pragma unroll
        for (int t = 0; t < 2; t++) {
            int r0 = m0 + wm * 32 + t * 16 + (lane >> 2);
            #pragma unroll
            for (int nt = 0; nt < 8; nt++) {
                int cl = clb + nt * 8 + (lane & 3) * 2;
                float2 bv = *(const float2*)(bias + cl);
                float2 o0, o1;
                o0.x = (acc[t][nt][0] + bv.x) * sc;
                o0.y = (acc[t][nt][1] + bv.y) * sc;
                o1.x = (acc[t][nt][2] + bv.x) * sc;
                o1.y = (acc[t][nt][3] + bv.y) * sc;
                *(float2*)(dstb + (size_t)r0 * 768 + cl)       = o0;
                *(float2*)(dstb + (size_t)(r0 + 8) * 768 + cl) = o1;
            }
        }
    } else {
        const int gcb = n0 + wn * 64;
        #pragma unroll
        for (int t = 0; t < 2; t++) {
            int r0 = m0 + wm * 32 + t * 16 + (lane >> 2);
            #pragma unroll
            for (int nt = 0; nt < 8; nt++) {
                int gc = gcb + nt * 8 + (lane & 3) * 2;
                float2 bv = *(const float2*)(b0 + gc);
                float2 o0, o1;
                o0.x = fmaxf(acc[t][nt][0] + bv.x, 0.f);
                o0.y = fmaxf(acc[t][nt][1] + bv.y, 0.f);
                o1.x = fmaxf(acc[t][nt][2] + bv.x, 0.f);
                o1.y = fmaxf(acc[t][nt][3] + bv.y, 0.f);
                *(float2*)(g_z + (size_t)r0 * 768 + gc)       = o0;
                *(float2*)(g_z + (size_t)(r0 + 8) * 768 + gc) = o1;
            }
        }
    }
}

// ===========================================================================
// K2: qk_hmma — S = Q·K^T + bias, 96 batches, tile 128x128, K=64.
// ===========================================================================
#define QK_SMEM 65536
__global__ __launch_bounds__(256) void qk_hmma(const float* __restrict__ bias)
{
    extern __shared__ char smem[];
    const int tid = threadIdx.x, wid = tid >> 5, lane = tid & 31;
    const int q0 = blockIdx.x * 128, k0 = blockIdx.y * 128;
    const int bh = blockIdx.z, b = bh / 12, h = bh % 12;
    const int wm = wid & 3, wn = wid >> 2;
    const uint32_t a_hi = smem_u32(smem);
    const uint32_t a_lo = a_hi + 16384, b_hi = a_hi + 32768, b_lo = a_hi + 49152;

    const float* Qb = g_q + (size_t)(b * 256 + q0) * 768 + h * 64;
    const float* Kb = g_k + (size_t)(b * 256 + k0) * 768 + h * 64;
    #pragma unroll
    for (int i = 0; i < 8; i++) {
        int fid = i * 256 + tid;
        int row = fid >> 4, c4 = fid & 15;
        uint32_t off = SMEM_SWZ((uint32_t)(row * 128 + c4 * 8));
        uint2 hi, lo;
        cvt_hilo(*(const float4*)(Qb + (size_t)row * 768 + c4 * 4), hi, lo);
        *(uint2*)(smem + off)         = hi;
        *(uint2*)(smem + 16384 + off) = lo;
        cvt_hilo(*(const float4*)(Kb + (size_t)row * 768 + c4 * 4), hi, lo);
        *(uint2*)(smem + 32768 + off) = hi;
        *(uint2*)(smem + 49152 + off) = lo;
    }
    __syncthreads();

    float acc[2][8][4];
    #pragma unroll
    for (int t = 0; t < 2; t++)
        #pragma unroll
        for (int n = 0; n < 8; n++)
            #pragma unroll
            for (int j = 0; j < 4; j++) acc[t][n][j] = 0.f;

    const int arow = wm * 32 + (lane & 15);
    const int brow = wn * 64 + (lane & 15);
    const int cbyt = (lane >> 4) * 16;
    #pragma unroll
    for (int ks = 0; ks < 4; ks++) {
        const int kb = ks * 32 + cbyt;
        uint32_t ah[2][4], al[2][4];
        #pragma unroll
        for (int t = 0; t < 2; t++) {
            uint32_t off = SMEM_SWZ((uint32_t)((arow + t * 16) * 128 + kb));
            LDSM4(ah[t], a_hi + off);
            LDSM4(al[t], a_lo + off);
        }
        uint32_t bhf[4][4], blf[4][4];
        #pragma unroll
        for (int g = 0; g < 4; g++) {
            uint32_t off = SMEM_SWZ((uint32_t)((brow + g * 16) * 128 + kb));
            LDSM4(bhf[g], b_hi + off);
            LDSM4(blf[g], b_lo + off);
        }
        #pragma unroll
        for (int t = 0; t < 2; t++)
            #pragma unroll
            for (int g = 0; g < 4; g++) {
                MMA16816(acc[t][2 * g + 0], ah[t], bhf[g][0], bhf[g][2]);
                MMA16816(acc[t][2 * g + 1], ah[t], bhf[g][1], bhf[g][3]);
                MMA16816(acc[t][2 * g + 0], ah[t], blf[g][0], blf[g][2]);
                MMA16816(acc[t][2 * g + 1], ah[t], blf[g][1], blf[g][3]);
                MMA16816(acc[t][2 * g + 0], al[t], bhf[g][0], bhf[g][2]);
                MMA16816(acc[t][2 * g + 1], al[t], bhf[g][1], bhf[g][3]);
            }
    }

    const size_t rbase = (size_t)bh * 256;
    #pragma unroll
    for (int t = 0; t < 2; t++) {
        int r0 = q0 + wm * 32 + t * 16 + (lane >> 2);
        #pragma unroll
        for (int nt = 0; nt < 8; nt++) {
            int cl = k0 + wn * 64 + nt * 8 + (lane & 3) * 2;
            size_t i0 = (rbase + r0) * 256 + cl;
            size_t i1 = (rbase + r0 + 8) * 256 + cl;
            float2 bv0 = *(const float2*)(bias + i0);
            float2 bv1 = *(const float2*)(bias + i1);
            float2 o0, o1;
            o0.x = acc[t][nt][0] + bv0.x;
            o0.y = acc[t][nt][1] + bv0.y;
            o1.x = acc[t][nt][2] + bv1.x;
            o1.y = acc[t][nt][3] + bv1.y;
            *(float2*)(g_sw + i0) = o0;
            *(float2*)(g_sw + i1) = o1;
        }
    }
}

// ===========================================================================
// K3: qw_hmma — qw[bq, h*128+p] = q[bq,h,:]·Wsk[p,:], fp16 out. grid (16,12).
// ===========================================================================
__global__ __launch_bounds__(256) void qw_hmma(const float* __restrict__ Wsk)
{
    extern __shared__ char smem[];
    const int tid = threadIdx.x, wid = tid >> 5, lane = tid & 31;
    const int m0 = blockIdx.x * 128;
    const int h  = blockIdx.y;
    const int wm = wid & 3, wn = wid >> 2;
    const uint32_t a_hi = smem_u32(smem);
    const uint32_t a_lo = a_hi + 16384, b_hi = a_hi + 32768, b_lo = a_hi + 49152;

    #pragma unroll
    for (int i = 0; i < 8; i++) {
        int fid = i * 256 + tid;
        int row = fid >> 4, c4 = fid & 15;
        uint32_t off = SMEM_SWZ((uint32_t)(row * 128 + c4 * 8));
        uint2 hi, lo;
        cvt_hilo(*(const float4*)(g_q + (size_t)(m0 + row) * 768 + h * 64 + c4 * 4), hi, lo);
        *(uint2*)(smem + off)         = hi;
        *(uint2*)(smem + 16384 + off) = lo;
        cvt_hilo(*(const float4*)(Wsk + row * 64 + c4 * 4), hi, lo);
        *(uint2*)(smem + 32768 + off) = hi;
        *(uint2*)(smem + 49152 + off) = lo;
    }
    __syncthreads();

    float acc[2][8][4];
    #pragma unroll
    for (int t = 0; t < 2; t++)
        #pragma unroll
        for (int n = 0; n < 8; n++)
            #pragma unroll
            for (int j = 0; j < 4; j++) acc[t][n][j] = 0.f;

    const int arow = wm * 32 + (lane & 15);
    const int brow = wn * 64 + (lane & 15);
    const int cbyt = (lane >> 4) * 16;
    #pragma unroll
    for (int ks = 0; ks < 4; ks++) {
        const int kb = ks * 32 + cbyt;
        uint32_t ah[2][4], al[2][4];
        #pragma unroll
        for (int t = 0; t < 2; t++) {
            uint32_t off = SMEM_SWZ((uint32_t)((arow + t * 16) * 128 + kb));
            LDSM4(ah[t], a_hi + off);
            LDSM4(al[t], a_lo + off);
        }
        uint32_t bhf[4][4], blf[4][4];
        #pragma unroll
        for (int g = 0; g < 4; g++) {
            uint32_t off = SMEM_SWZ((uint32_t)((brow + g * 16) * 128 + kb));
            LDSM4(bhf[g], b_hi + off);
            LDSM4(blf[g], b_lo + off);
        }
        #pragma unroll
        for (int t = 0; t < 2; t++)
            #pragma unroll
            for (int g = 0; g < 4; g++) {
                MMA16816(acc[t][2 * g + 0], ah[t], bhf[g][0], bhf[g][2]);
                MMA16816(acc[t][2 * g + 1], ah[t], bhf[g][1], bhf[g][3]);
                MMA16816(acc[t][2 * g + 0], ah[t], blf[g][0], blf[g][2]);
                MMA16816(acc[t][2 * g + 1], ah[t], blf[g][1], blf[g][3]);
                MMA16816(acc[t][2 * g + 0], al[t], bhf[g][0], bhf[g][2]);
                MMA16816(acc[t][2 * g + 1], al[t], bhf[g][1], bhf[g][3]);
            }
    }

    #pragma unroll
    for (int t = 0; t < 2; t++) {
        int r0 = m0 + wm * 32 + t * 16 + (lane >> 2);
        #pragma unroll
        for (int nt = 0; nt < 8; nt++) {
            int cl = h * 128 + wn * 64 + nt * 8 + (lane & 3) * 2;
            *(__half2*)(g_qwh + (size_t)r0 * 1536 + cl) =
                __floats2half2_rn(acc[t][nt][0], acc[t][nt][1]);
            *(__half2*)(g_qwh + (size_t)(r0 + 8) * 1536 + cl) =
                __floats2half2_rn(acc[t][nt][2], acc[t][nt][3]);
        }
    }
}

// ===========================================================================
// K3b: qc[bq,h] = q[bq,h,:]·bsk. grid 128, block 192.
// ===========================================================================
__global__ __launch_bounds__(192) void qc_kernel(const float* __restrict__ bsk)
{
    __shared__ float bs[64];
    const int tid = threadIdx.x;
    if (tid < 64) bs[tid] = bsk[tid];
    __syncthreads();
    const int r = blockIdx.x * 16 + tid / 12;
    const int h = tid % 12;
    const float* q = g_q + (size_t)r * 768 + h * 64;
    float a = 0.f;
    #pragma unroll 8
    for (int d = 0; d < 64; d++) a += q[d] * bs[d];
    g_qc[(size_t)r * 12 + h] = a;
}

// ===========================================================================
// K4: attn_struct — per (b,q) CTA; pn fp16; HMMA phases C and E.
// ===========================================================================
#define PN_STR 136
#define QW_STR 136
#define WH_STR 264
#define OFF_QWH 69632
#define OFF_WH  73984
#define OFF_SS  82432
#define OFF_QCV 94720
#define AT_SMEM 94784
__global__ __launch_bounds__(512, 2) void attn_struct_kernel(
    const float* __restrict__ paths,
    const float* __restrict__ Wsv, const float* __restrict__ bsv,
    const float* __restrict__ gpath, const float* __restrict__ bpath)
{
    extern __shared__ char smraw[];
    __half* pn  = (__half*)smraw;
    __half* qwh = (__half*)(smraw + OFF_QWH);
    __half* wh  = (__half*)(smraw + OFF_WH);
    float*  ss  = (float*)(smraw + OFF_SS);       // scores, later wp
    float*  qcv = (float*)(smraw + OFF_QCV);
    const uint32_t pn_u  = smem_u32(pn);
    const uint32_t qwh_u = smem_u32(qwh);
    const uint32_t wh_u  = smem_u32(wh);

    const int b  = blockIdx.y;
    const int qi = blockIdx.x;
    const int bq = b * 256 + qi;
    const int tid  = threadIdx.x;
    const int warp = tid >> 5;
    const int lane = tid & 31;

    // ---- init: qwh from g_qwh (fp16), zero pads, qcv ----
    if (tid < 192) {
        uint4 v = *(const uint4*)(g_qwh + (size_t)bq * 1536 + tid * 8);
        int h = (tid * 8) >> 7, p = (tid * 8) & 127;
        *(uint4*)(qwh + h * QW_STR + p) = v;
    } else {
        int t = tid - 192;   // 0..319
        __half2 z = __half2half2(__float2half(0.f));
        if (t < 272) *((__half2*)(qwh + 12 * QW_STR) + t) = z;
        #pragma unroll
        for (int i = 0; i < 2; i++) {
            int o = t + i * 320;
            if (o < 528) *((__half2*)(wh + 12 * WH_STR) + o) = z;
        }
    }
    if (tid < 12) qcv[tid] = g_qc[(size_t)bq * 12 + tid];

    // ---- Phase A: layernorm paths rows into pn (fp16, stride 136) ----
    {
        float4 gp = *(const float4*)(gpath + lane * 4);
        float4 bp = *(const float4*)(bpath + lane * 4);
        const float* prow = paths + (size_t)bq * 32768;
        #pragma unroll
        for (int half_ = 0; half_ < 2; half_++) {
            float4 xv[8];
            #pragma unroll
            for (int i = 0; i < 8; i++) {
                int r = half_ * 128 + i * 16 + warp;
                xv[i] = *(const float4*)(prow + r * 128 + lane * 4);
            }
            #pragma unroll
            for (int i = 0; i < 8; i++) {
                int r = half_ * 128 + i * 16 + warp;
                float s  = xv[i].x + xv[i].y + xv[i].z + xv[i].w;
                float sq = xv[i].x * xv[i].x + xv[i].y * xv[i].y +
                           xv[i].z * xv[i].z + xv[i].w * xv[i].w;
                #pragma unroll
                for (int o = 16; o > 0; o >>= 1) {
                    s  += __shfl_xor_sync(0xffffffffu, s,  o);
                    sq += __shfl_xor_sync(0xffffffffu, sq, o);
                }
                float mu  = s * 0.0078125f;
                float var = sq * 0.0078125f - mu * mu;
                float rs  = rsqrtf(var + EPS);
                float y0 = (xv[i].x - mu) * rs * gp.x + bp.x;
                float y1 = (xv[i].y - mu) * rs * gp.y + bp.y;
                float y2 = (xv[i].z - mu) * rs * gp.z + bp.z;
                float y3 = (xv[i].w - mu) * rs * gp.w + bp.w;
                __half* pr = pn + r * PN_STR + lane * 4;
                *(__half2*)(pr)     = __floats2half2_rn(y0, y1);
                *(__half2*)(pr + 2) = __floats2half2_rn(y2, y3);
            }
        }
    }
    __syncthreads();

    // ---- Phase C (HMMA): ss[h][key] = qw[h,:]·pn[key,:] + qc[h] + content ----
    {
        const int n0 = warp * 16;
        const uint32_t aaddr = qwh_u + ((lane & 15) * QW_STR + (lane >> 4) * 8) * 2;
        const uint32_t baddr = pn_u + ((n0 + (lane & 15)) * PN_STR + (lane >> 4) * 8) * 2;
        float c0[4] = {0.f, 0.f, 0.f, 0.f};
        float c1[4] = {0.f, 0.f, 0.f, 0.f};
        #pragma unroll
        for (int kc = 0; kc < 8; kc++) {
            uint32_t a[4], bm[4];
            LDSM4(a, aaddr + kc * 32);
            LDSM4(bm, baddr + kc * 32);
            MMA16816H(c0, a, bm[0], bm[2]);
            MMA16816H(c1, a, bm[1], bm[3]);
        }
        const int h0 = lane >> 2;
        const int kk = (lane & 3) * 2;
        const float* swb = g_sw + ((size_t)(b * 12 + h0) * 256 + qi) * 256;
        {
            float2 s0 = *(const float2*)(swb + n0 + kk);
            float2 s1 = *(const float2*)(swb + n0 + 8 + kk);
            float qc0 = qcv[h0];
            ss[h0 * 256 + n0 + kk]     = c0[0] + qc0 + s0.x;
            ss[h0 * 256 + n0 + kk + 1] = c0[1] + qc0 + s0.y;
            ss[h0 * 256 + n0 + 8 + kk]     = c1[0] + qc0 + s1.x;
            ss[h0 * 256 + n0 + 8 + kk + 1] = c1[1] + qc0 + s1.y;
        }
        if (h0 < 4) {
            const int h1 = h0 + 8;
            const float* swb1 = g_sw + ((size_t)(b * 12 + h1) * 256 + qi) * 256;
            float2 s0 = *(const float2*)(swb1 + n0 + kk);
            float2 s1 = *(const float2*)(swb1 + n0 + 8 + kk);
            float qc1 = qcv[h1];
            ss[h1 * 256 + n0 + kk]     = c0[2] + qc1 + s0.x;
            ss[h1 * 256 + n0 + kk + 1] = c0[3] + qc1 + s0.y;
            ss[h1 * 256 + n0 + 8 + kk]     = c1[2] + qc1 + s1.x;
            ss[h1 * 256 + n0 + 8 + kk + 1] = c1[3] + qc1 + s1.y;
        }
    }
    __syncthreads();

    // ---- Phase D: softmax; fp16 weights -> g_swh and wh ----
    if (warp < 12) {
        float* row = ss + warp * 256;
        float vals[8], m = -1e30f;
        #pragma unroll
        for (int i = 0; i < 8; i++) {
            vals[i] = row[lane + i * 32];
            m = fmaxf(m, vals[i]);
        }
        #pragma unroll
        for (int o = 16; o > 0; o >>= 1)
            m = fmaxf(m, __shfl_xor_sync(0xffffffffu, m, o));
        float s = 0.f;
        #pragma unroll
        for (int i = 0; i < 8; i++) { vals[i] = __expf(vals[i] - m); s += vals[i]; }
        #pragma unroll
        for (int o = 16; o > 0; o >>= 1)
            s += __shfl_xor_sync(0xffffffffu, s, o);
        float inv = 1.f / s;
        __half* gwh = g_swh + ((size_t)(b * 12 + warp) * 256 + qi) * 256;
        __half* whr = wh + warp * WH_STR;
        #pragma unroll
        for (int i = 0; i < 8; i++) {
            __half w = __float2half_rn(vals[i] * inv);
            gwh[lane + i * 32] = w;
            whr[lane + i * 32] = w;
        }
    }
    __syncthreads();

    // ---- Phase E (HMMA): wp[h][p] = Σ_k w[h,k]·pn[k,p]  (wp aliases ss) ----
    {
        const int p0 = warp * 8;
        const uint32_t aaddr = wh_u + ((lane & 15) * WH_STR + (lane >> 4) * 8) * 2;
        const uint32_t baddr = pn_u + ((lane & 15) * PN_STR + p0) * 2;
        float c[4] = {0.f, 0.f, 0.f, 0.f};
        #pragma unroll
        for (int kc = 0; kc < 16; kc++) {
            uint32_t a[4], bm[2];
            LDSM4(a, aaddr + kc * 32);
            LDSM2T(bm, baddr + kc * 16 * PN_STR * 2);
            MMA16816H(c, a, bm[0], bm[1]);
        }
        __syncthreads();
        float* wp = ss;
        const int h0 = lane >> 2;
        const int pp = p0 + (lane & 3) * 2;
        wp[h0 * 128 + pp]     = c[0];
        wp[h0 * 128 + pp + 1] = c[1];
        if (h0 < 4) {
            wp[(h0 + 8) * 128 + pp]     = c[2];
            wp[(h0 + 8) * 128 + pp + 1] = c[3];
        }
    }
    __syncthreads();

    // ---- Phase F: struct out[h,d] = Σ_p wp[h,p]*Wsv[p,d] + bsv[d] ----
    const float* wp = ss;
    float* aout = g_attn + (size_t)bq * 768;
    #pragma unroll
    for (int e = 0; e < 2; e++) {
        int o = tid + e * 512;
        if (o < 768) {
            int h = o >> 6, d = o & 63;
            const float* wpr = wp + h * 128;
            float acc = 0.f;
            #pragma unroll 8
            for (int p = 0; p < 128; p++)
                acc += wpr[p] * Wsv[p * 64 + d];
            aout[o] = acc + bsv[d];
        }
    }
}

// ===========================================================================
// K5: wv_hmma — g_attn += W(fp16) @ V(hi/lo fp16). grid (2, 96).
// smem: W 128x64 fp16 (16K, swizzled) | V_hi 64x72h (9216) | V_lo (9216)
// ===========================================================================
#define WV_SMEM 34816
#define V_STR 72
__global__ __launch_bounds__(256) void wv_hmma()
{
    extern __shared__ char smem[];
    const int tid = threadIdx.x, wid = tid >> 5, lane = tid & 31;
    const int q0 = blockIdx.x * 128;
    const int bh = blockIdx.y, b = bh / 12, h = bh % 12;
    const int wm = wid & 3, wn = wid >> 2;
    const uint32_t w_u = smem_u32(smem);
    const uint32_t vh_u = w_u + 16384;
    const uint32_t vl_u = w_u + 16384 + 9216;

    float acc[2][4][4];
    #pragma unroll
    for (int t = 0; t < 2; t++)
        #pragma unroll
        for (int g = 0; g < 4; g++)
            #pragma unroll
            for (int j = 0; j < 4; j++) acc[t][g][j] = 0.f;

    const __half* Wb = g_swh + ((size_t)bh * 256 + q0) * 256;
    const float* Vb = g_v + (size_t)(b * 256) * 768 + h * 64;

    for (int kc = 0; kc < 4; kc++) {
        #pragma unroll
        for (int i = 0; i < 4; i++) {
            int fid = i * 256 + tid;
            int row = fid >> 3, c8 = fid & 7;
            uint4 v = *(const uint4*)(Wb + (size_t)row * 256 + kc * 64 + c8 * 8);
            *(uint4*)(smem + SMEM_SWZ((uint32_t)(row * 128 + c8 * 16))) = v;
        }
        #pragma unroll
        for (int i = 0; i < 4; i++) {
            int fid = i * 256 + tid;
            int row = fid >> 4, c4 = fid & 15;
            float4 v = *(const float4*)(Vb + (size_t)(kc * 64 + row) * 768 + c4 * 4);
            __half h0 = __float2half(v.x), h1 = __float2half(v.y);
            __half h2 = __float2half(v.z), h3 = __float2half(v.w);
            __half l0 = __float2half(v.x - __half2float(h0));
            __half l1 = __float2half(v.y - __half2float(h1));
            __half l2 = __float2half(v.z - __half2float(h2));
            __half l3 = __float2half(v.w - __half2float(h3));
            uint32_t off = (uint32_t)(row * V_STR + c4 * 4) * 2;
            *(uint2*)(smem + 16384 + off)        = make_uint2(pack2h(h0, h1), pack2h(h2, h3));
            *(uint2*)(smem + 16384 + 9216 + off) = make_uint2(pack2h(l0, l1), pack2h(l2, l3));
        }
        __syncthreads();

        #pragma unroll
        for (int ks = 0; ks < 4; ks++) {
            uint32_t a[2][4];
            #pragma unroll
            for (int t = 0; t < 2; t++) {
                uint32_t off = SMEM_SWZ((uint32_t)((wm * 32 + (lane & 15) + t * 16) * 128 +
                                                   ks * 32 + (lane >> 4) * 16));
                LDSM4(a[t], w_u + off);
            }
            #pragma unroll
            for (int g = 0; g < 4; g++) {
                uint32_t boff = (uint32_t)((ks * 16 + (lane & 15)) * V_STR +
                                           wn * 32 + g * 8) * 2;
                uint32_t bhv[2], blv[2];
                LDSM2T(bhv, vh_u + boff);
                LDSM2T(blv, vl_u + boff);
                #pragma unroll
                for (int t = 0; t < 2; t++) {
                    MMA16816H(acc[t][g], a[t], bhv[0], bhv[1]);
                    MMA16816H(acc[t][g], a[t], blv[0], blv[1]);
                }
            }
        }
        __syncthreads();
    }

    #pragma unroll
    for (int t = 0; t < 2; t++) {
        int r0 = q0 + wm * 32 + t * 16 + (lane >> 2);
        #pragma unroll
        for (int g = 0; g < 4; g++) {
            int col = h * 64 + wn * 32 + g * 8 + (lane & 3) * 2;
            float* d0 = g_attn + ((size_t)(b * 256) + r0) * 768 + col;
            float* d1 = d0 + 8 * 768;
            float2 o0 = *(float2*)d0, o1 = *(float2*)d1;
            o0.x += acc[t][g][0]; o0.y += acc[t][g][1];
            o1.x += acc[t][g][2]; o1.y += acc[t][g][3];
            *(float2*)d0 = o0;
            *(float2*)d1 = o1;
        }
    }
}

// ===========================================================================
// K8: out = LN(nodes + g_z). One warp per row.
// ===========================================================================
__global__ __launch_bounds__(256) void final_ln(
    const float* __restrict__ nodes,
    const float* __restrict__ gout, const float* __restrict__ bout,
    float* __restrict__ out)
{
    const int row  = blockIdx.x * 8 + (threadIdx.x >> 5);
    const int lane = threadIdx.x & 31;
    const float* x1 = nodes + (size_t)row * 768;
    const float* x2 = g_z   + (size_t)row * 768;

    float v[24];
    float s = 0.f, sq = 0.f;
    #pragma unroll
    for (int i = 0; i < 6; i++) {
        float4 a = *(const float4*)(x1 + i * 128 + lane * 4);
        float4 c = *(const float4*)(x2 + i * 128 + lane * 4);
        float t0 = a.x + c.x, t1 = a.y + c.y, t2 = a.z + c.z, t3 = a.w + c.w;
        v[i * 4 + 0] = t0; v[i * 4 + 1] = t1; v[i * 4 + 2] = t2; v[i * 4 + 3] = t3;
        s += t0 + t1 + t2 + t3;
        sq += t0 * t0 + t1 * t1 + t2 * t2 + t3 * t3;
    }
    #pragma unroll
    for (int o = 16; o > 0; o >>= 1) {
        s  += __shfl_xor_sync(0xffffffffu, s,  o);
        sq += __shfl_xor_sync(0xffffffffu, sq, o);
    }
    const float inv = 1.f / 768.f;
    float mu  = s * inv;
    float var = sq * inv - mu * mu;
    float rs  = rsqrtf(var + EPS);

    float* orow = out + (size_t)row * 768;
    #pragma unroll
    for (int i = 0; i < 6; i++) {
        int idx = i * 128 + lane * 4;
        float4 g4 = *(const float4*)(gout + idx);
        float4 b4 = *(const float4*)(bout + idx);
        float4 r;
        r.x = (v[i * 4 + 0] - mu) * rs * g4.x + b4.x;
        r.y = (v[i * 4 + 1] - mu) * rs * g4.y + b4.y;
        r.z = (v[i * 4 + 2] - mu) * rs * g4.z + b4.z;
        r.w = (v[i * 4 + 3] - mu) * rs * g4.w + b4.w;
        *(float4*)(orow + idx) = r;
    }
}

// ===========================================================================
extern "C" void kernel_launch(void* const* d_in, const int* in_sizes, int n_in,
                              void* d_out, int out_size)
{
    const float* nodes = (const float*)d_in[0];
    const float* bias  = (const float*)d_in[1];
    const float* paths = (const float*)d_in[2];
    const float* Wq  = (const float*)d_in[3];
    const float* bq  = (const float*)d_in[4];
    const float* Wk  = (const float*)d_in[5];
    const float* bk  = (const float*)d_in[6];
    const float* Wv  = (const float*)d_in[7];
    const float* bv  = (const float*)d_in[8];
    const float* Wsk = (const float*)d_in[9];
    const float* bsk = (const float*)d_in[10];
    const float* Wsv = (const float*)d_in[11];
    const float* bsv = (const float*)d_in[12];
    const float* Wo  = (const float*)d_in[13];
    const float* bo  = (const float*)d_in[14];
    const float* gpath = (const float*)d_in[15];
    const float* bpath = (const float*)d_in[16];
    const float* gout  = (const float*)d_in[17];
    const float* bout  = (const float*)d_in[18];
    float* out = (float*)d_out;

    static bool attr_set = false;
    if (!attr_set) {
        cudaFuncSetAttribute(attn_struct_kernel,
                             cudaFuncAttributeMaxDynamicSharedMemorySize, AT_SMEM);
        cudaFuncSetAttribute(hmma_gemm,
                             cudaFuncAttributeMaxDynamicSharedMemorySize, HG_SMEM);
        cudaFuncSetAttribute(qk_hmma,
                             cudaFuncAttributeMaxDynamicSharedMemorySize, QK_SMEM);
        cudaFuncSetAttribute(qw_hmma,
                             cudaFuncAttributeMaxDynamicSharedMemorySize, QK_SMEM);
        attr_set = true;
    }

    float* fa_global;
    cudaGetSymbolAddress((void**)&fa_global, g_attn);

    prep_weights<<<dim3(48, 12), 256>>>(Wq, Wk, Wv, Wo);
    hmma_gemm<<<dim3(18, 16), 256, HG_SMEM>>>(nodes, 0, bq, bk, bv, 0);
    qk_hmma<<<dim3(2, 2, 96), 256, QK_SMEM>>>(bias);
    qw_hmma<<<dim3(16, 12), 256, QK_SMEM>>>(Wsk);
    qc_kernel<<<128, 192>>>(bsk);
    attn_struct_kernel<<<dim3(256, 8), 512, AT_SMEM>>>(
        paths, Wsv, bsv, gpath, bpath);
    wv_hmma<<<dim3(2, 96), 256, WV_SMEM>>>();
    hmma_gemm<<<dim3(6, 16), 256, HG_SMEM>>>(fa_global, 2304, bo, bo, bo, 1);
    final_ln<<<256, 256>>>(nodes, gout, bout, out);
}